// round 1
// baseline (speedup 1.0000x reference)
#include <cuda_runtime.h>
#include <math.h>

#define Bdim 4
#define Sdim 2048
#define Hdim 512
#define NH   8
#define HD   64
#define H3   1536

// Static scratch (allocation-guard-safe)
__device__ float g_qkv[(size_t)Bdim * Sdim * H3];            // 50 MB: [b,s, 3*512] (q|k|v, each [h*64+d])
__device__ float g_scores[(size_t)Bdim * NH * Sdim * Sdim];  // 537 MB: [b,h,q,k] scores -> weights
__device__ float g_ctx[(size_t)Bdim * Sdim * Hdim];          // 17 MB: [b,q, h*64+d]

// ---------------------------------------------------------------------------
// Generic C[M,N] = A[M,K] @ B[N,K]^T + bias[N]   (all row-major)
// Block tile 128x64, K-chunk 16, 256 threads, 8x4 microtile.
// ---------------------------------------------------------------------------
__global__ void __launch_bounds__(256) gemm_abT_kernel(
    const float* __restrict__ A, const float* __restrict__ B,
    const float* __restrict__ bias, float* __restrict__ C,
    int M, int N, int K)
{
    __shared__ __align__(16) float As[16][128];
    __shared__ __align__(16) float Bs[16][64];

    const int tid = threadIdx.x;
    const int tx = tid & 15, ty = tid >> 4;
    const int m0 = blockIdx.y * 128;
    const int n0 = blockIdx.x * 64;

    const int arow = tid & 127, ahalf = tid >> 7;
    const int brow = tid >> 2,  bq    = tid & 3;

    float acc[8][4];
#pragma unroll
    for (int i = 0; i < 8; i++)
#pragma unroll
        for (int j = 0; j < 4; j++) acc[i][j] = 0.f;

    for (int kc = 0; kc < K; kc += 16) {
#pragma unroll
        for (int p = 0; p < 2; p++) {
            int koff = (ahalf * 2 + p) * 4;
            float4 v = *(const float4*)&A[(size_t)(m0 + arow) * K + kc + koff];
            As[koff + 0][arow] = v.x; As[koff + 1][arow] = v.y;
            As[koff + 2][arow] = v.z; As[koff + 3][arow] = v.w;
        }
        {
            float4 v = *(const float4*)&B[(size_t)(n0 + brow) * K + kc + bq * 4];
            Bs[bq * 4 + 0][brow] = v.x; Bs[bq * 4 + 1][brow] = v.y;
            Bs[bq * 4 + 2][brow] = v.z; Bs[bq * 4 + 3][brow] = v.w;
        }
        __syncthreads();
#pragma unroll
        for (int kk = 0; kk < 16; kk++) {
            float4 b4 = *(const float4*)&Bs[kk][tx * 4];
            float4 a0 = *(const float4*)&As[kk][ty * 8];
            float4 a1 = *(const float4*)&As[kk][ty * 8 + 4];
            float av[8] = {a0.x, a0.y, a0.z, a0.w, a1.x, a1.y, a1.z, a1.w};
            float bv[4] = {b4.x, b4.y, b4.z, b4.w};
#pragma unroll
            for (int i = 0; i < 8; i++)
#pragma unroll
                for (int j = 0; j < 4; j++)
                    acc[i][j] = fmaf(av[i], bv[j], acc[i][j]);
        }
        __syncthreads();
    }

    const int nb = n0 + tx * 4;
    float4 bvec = *(const float4*)&bias[nb];
#pragma unroll
    for (int i = 0; i < 8; i++) {
        int m = m0 + ty * 8 + i;
        float4 o;
        o.x = acc[i][0] + bvec.x;
        o.y = acc[i][1] + bvec.y;
        o.z = acc[i][2] + bvec.z;
        o.w = acc[i][3] + bvec.w;
        *(float4*)&C[(size_t)m * N + nb] = o;
    }
}

// ---------------------------------------------------------------------------
// Scores: S[b,h,q,k] = 0.125*(q.k - dist2(q,k)) ; masked -> -1e30
// Block = one 64x64 (q,k) tile of one (b,h). 256 threads, 4x4 microtile.
// ---------------------------------------------------------------------------
__global__ void __launch_bounds__(256) scores_kernel(
    const float* __restrict__ pos, const int* __restrict__ mask)
{
    const int bh = blockIdx.z;
    const int b = bh >> 3, h = bh & 7;
    const int q0 = blockIdx.y * 64, k0 = blockIdx.x * 64;

    __shared__ __align__(16) float Qs[64][64];
    __shared__ __align__(16) float Ks[64][64];
    __shared__ float Pq[64][3], Pk[64][3];
    __shared__ int   Mk[64];

    const int tid = threadIdx.x;
    {
        int row = tid & 63;
        int f0 = (tid >> 6) * 4;
        const float* qrow = g_qkv + (size_t)(b * Sdim + q0 + row) * H3 + h * HD;
        const float* krow = g_qkv + (size_t)(b * Sdim + k0 + row) * H3 + 512 + h * HD;
#pragma unroll
        for (int j = 0; j < 4; j++) {
            int d = (f0 + j) * 4;
            float4 v = *(const float4*)&qrow[d];
            Qs[d][row] = v.x; Qs[d + 1][row] = v.y; Qs[d + 2][row] = v.z; Qs[d + 3][row] = v.w;
            float4 w = *(const float4*)&krow[d];
            Ks[d][row] = w.x; Ks[d + 1][row] = w.y; Ks[d + 2][row] = w.z; Ks[d + 3][row] = w.w;
        }
    }
    if (tid < 64) {
        Pq[tid][0] = pos[(size_t)(b * Sdim + q0 + tid) * 3 + 0];
        Pq[tid][1] = pos[(size_t)(b * Sdim + q0 + tid) * 3 + 1];
        Pq[tid][2] = pos[(size_t)(b * Sdim + q0 + tid) * 3 + 2];
        Pk[tid][0] = pos[(size_t)(b * Sdim + k0 + tid) * 3 + 0];
        Pk[tid][1] = pos[(size_t)(b * Sdim + k0 + tid) * 3 + 1];
        Pk[tid][2] = pos[(size_t)(b * Sdim + k0 + tid) * 3 + 2];
        Mk[tid]    = mask[b * Sdim + k0 + tid];
    }
    __syncthreads();

    const int tx = tid & 15, ty = tid >> 4;
    float acc[4][4];
#pragma unroll
    for (int i = 0; i < 4; i++)
#pragma unroll
        for (int j = 0; j < 4; j++) acc[i][j] = 0.f;

#pragma unroll 8
    for (int d = 0; d < 64; d++) {
        float4 a = *(const float4*)&Qs[d][ty * 4];
        float4 bb = *(const float4*)&Ks[d][tx * 4];
        float av[4] = {a.x, a.y, a.z, a.w};
        float bv[4] = {bb.x, bb.y, bb.z, bb.w};
#pragma unroll
        for (int i = 0; i < 4; i++)
#pragma unroll
            for (int j = 0; j < 4; j++)
                acc[i][j] = fmaf(av[i], bv[j], acc[i][j]);
    }

#pragma unroll
    for (int i = 0; i < 4; i++) {
        int q = q0 + ty * 4 + i;
        float px = Pq[ty * 4 + i][0], py = Pq[ty * 4 + i][1], pz = Pq[ty * 4 + i][2];
        float o[4];
#pragma unroll
        for (int j = 0; j < 4; j++) {
            int kk = tx * 4 + j;
            float dx = px - Pk[kk][0];
            float dy = py - Pk[kk][1];
            float dz = pz - Pk[kk][2];
            float d2 = dx * dx + dy * dy + dz * dz;
            float s = 0.125f * (acc[i][j] - d2);
            if (Mk[kk] == 0) s = -1e30f;
            o[j] = s;
        }
        float4 ov = {o[0], o[1], o[2], o[3]};
        *(float4*)&g_scores[((size_t)bh * Sdim + q) * Sdim + k0 + tx * 4] = ov;
    }
}

// ---------------------------------------------------------------------------
// Softmax in place (all 8 heads of one (b,q)) + head-mean write.
// Each thread owns 8 consecutive k for all heads (deterministic mean, no atomics).
// ---------------------------------------------------------------------------
__global__ void __launch_bounds__(256) softmax_mean_kernel(float* __restrict__ mean_out)
{
    const int bq = blockIdx.x;
    const int b = bq >> 11, q = bq & 2047;
    const int tid = threadIdx.x;
    const int lane = tid & 31, wid = tid >> 5;
    const int kbase = tid * 8;

    __shared__ float red[8];

    float macc[8];
#pragma unroll
    for (int j = 0; j < 8; j++) macc[j] = 0.f;

    for (int h = 0; h < NH; h++) {
        float* row = g_scores + ((size_t)((b * NH + h) * Sdim + q)) * Sdim;
        float4 v0 = *(const float4*)&row[kbase];
        float4 v1 = *(const float4*)&row[kbase + 4];
        float v[8] = {v0.x, v0.y, v0.z, v0.w, v1.x, v1.y, v1.z, v1.w};

        float m = v[0];
#pragma unroll
        for (int j = 1; j < 8; j++) m = fmaxf(m, v[j]);
#pragma unroll
        for (int off = 16; off > 0; off >>= 1)
            m = fmaxf(m, __shfl_xor_sync(0xffffffffu, m, off));
        if (lane == 0) red[wid] = m;
        __syncthreads();
        m = red[0];
#pragma unroll
        for (int w = 1; w < 8; w++) m = fmaxf(m, red[w]);
        __syncthreads();

        float e[8];
        float s = 0.f;
#pragma unroll
        for (int j = 0; j < 8; j++) { e[j] = __expf(v[j] - m); s += e[j]; }
#pragma unroll
        for (int off = 16; off > 0; off >>= 1)
            s += __shfl_xor_sync(0xffffffffu, s, off);
        if (lane == 0) red[wid] = s;
        __syncthreads();
        s = red[0];
#pragma unroll
        for (int w = 1; w < 8; w++) s += red[w];

        float inv = 1.0f / s;
        float wv[8];
#pragma unroll
        for (int j = 0; j < 8; j++) { wv[j] = e[j] * inv; macc[j] += wv[j]; }
        float4 o0 = {wv[0], wv[1], wv[2], wv[3]};
        float4 o1 = {wv[4], wv[5], wv[6], wv[7]};
        *(float4*)&row[kbase] = o0;
        *(float4*)&row[kbase + 4] = o1;
        __syncthreads();  // red reused next head
    }

    float* mrow = mean_out + ((size_t)(b * Sdim + q)) * Sdim + kbase;
    float4 m0 = {macc[0] * 0.125f, macc[1] * 0.125f, macc[2] * 0.125f, macc[3] * 0.125f};
    float4 m1 = {macc[4] * 0.125f, macc[5] * 0.125f, macc[6] * 0.125f, macc[7] * 0.125f};
    *(float4*)&mrow[0] = m0;
    *(float4*)&mrow[4] = m1;
}

// ---------------------------------------------------------------------------
// ctx[b,q, h*64+d] = sum_k W[b,h,q,k] * V[b,h,k,d]
// Block: 128 q-rows x full 64 d of one (b,h). K-chunk 16.
// ---------------------------------------------------------------------------
__global__ void __launch_bounds__(256) pv_kernel()
{
    const int bh = blockIdx.z;
    const int b = bh >> 3, h = bh & 7;
    const float* A = g_scores + (size_t)bh * Sdim * Sdim;  // normalized weights [S,S]
    const int m0 = blockIdx.x * 128;

    __shared__ __align__(16) float As[16][128];
    __shared__ __align__(16) float Vs[16][64];

    const int tid = threadIdx.x;
    const int tx = tid & 15, ty = tid >> 4;
    const int arow = tid & 127, ahalf = tid >> 7;
    const int vkk = tid >> 4, vfj = tid & 15;

    float acc[8][4];
#pragma unroll
    for (int i = 0; i < 8; i++)
#pragma unroll
        for (int j = 0; j < 4; j++) acc[i][j] = 0.f;

    for (int kc = 0; kc < Sdim; kc += 16) {
#pragma unroll
        for (int p = 0; p < 2; p++) {
            int koff = (ahalf * 2 + p) * 4;
            float4 v = *(const float4*)&A[(size_t)(m0 + arow) * Sdim + kc + koff];
            As[koff + 0][arow] = v.x; As[koff + 1][arow] = v.y;
            As[koff + 2][arow] = v.z; As[koff + 3][arow] = v.w;
        }
        {
            float4 v = *(const float4*)&g_qkv[(size_t)(b * Sdim + kc + vkk) * H3 + 1024 + h * HD + vfj * 4];
            *(float4*)&Vs[vkk][vfj * 4] = v;
        }
        __syncthreads();
#pragma unroll
        for (int kk = 0; kk < 16; kk++) {
            float4 b4 = *(const float4*)&Vs[kk][tx * 4];
            float4 a0 = *(const float4*)&As[kk][ty * 8];
            float4 a1 = *(const float4*)&As[kk][ty * 8 + 4];
            float av[8] = {a0.x, a0.y, a0.z, a0.w, a1.x, a1.y, a1.z, a1.w};
            float bv[4] = {b4.x, b4.y, b4.z, b4.w};
#pragma unroll
            for (int i = 0; i < 8; i++)
#pragma unroll
                for (int j = 0; j < 4; j++)
                    acc[i][j] = fmaf(av[i], bv[j], acc[i][j]);
        }
        __syncthreads();
    }

#pragma unroll
    for (int i = 0; i < 8; i++) {
        int m = m0 + ty * 8 + i;
        float4 o = {acc[i][0], acc[i][1], acc[i][2], acc[i][3]};
        *(float4*)&g_ctx[(size_t)(b * Sdim + m) * Hdim + h * HD + tx * 4] = o;
    }
}

// ---------------------------------------------------------------------------
extern "C" void kernel_launch(void* const* d_in, const int* in_sizes, int n_in,
                              void* d_out, int out_size)
{
    const float* x     = (const float*)d_in[0];
    const float* pos   = (const float*)d_in[1];
    const int*   mask  = (const int*)d_in[2];
    const float* w_qkv = (const float*)d_in[3];
    const float* b_qkv = (const float*)d_in[4];
    const float* w_out = (const float*)d_in[5];
    const float* b_out = (const float*)d_in[6];

    float* out_proj = (float*)d_out;                               // [B,S,H]
    float* mean_out = out_proj + (size_t)Bdim * Sdim * Hdim;       // [B,S,S]

    float *p_qkv, *p_ctx;
    cudaGetSymbolAddress((void**)&p_qkv, g_qkv);
    cudaGetSymbolAddress((void**)&p_ctx, g_ctx);

    // K1: QKV projection  [8192,1536] = x[8192,512] @ w_qkv^T + b_qkv
    {
        dim3 grid(H3 / 64, (Bdim * Sdim) / 128);
        gemm_abT_kernel<<<grid, 256>>>(x, w_qkv, b_qkv, p_qkv,
                                       Bdim * Sdim, H3, Hdim);
    }
    // K2: scores + bias + mask
    {
        dim3 grid(Sdim / 64, Sdim / 64, Bdim * NH);
        scores_kernel<<<grid, 256>>>(pos, mask);
    }
    // K3: softmax (in place) + head-mean
    softmax_mean_kernel<<<Bdim * Sdim, 256>>>(mean_out);

    // K4: ctx = W @ V
    {
        dim3 grid(Sdim / 128, 1, Bdim * NH);
        pv_kernel<<<grid, 256>>>();
    }
    // K5: output projection  [8192,512] = ctx @ w_out^T + b_out
    {
        dim3 grid(Hdim / 64, (Bdim * Sdim) / 128);
        gemm_abT_kernel<<<grid, 256>>>(p_ctx, w_out, b_out, out_proj,
                                       Bdim * Sdim, Hdim, Hdim);
    }
}

// round 2
// speedup vs baseline: 1.1777x; 1.1777x over previous
#include <cuda_runtime.h>
#include <math.h>

#define Bdim 4
#define Sdim 2048
#define Hdim 512
#define NH   8
#define HD   64
#define H3   1536

typedef unsigned long long ull;

// Static scratch (allocation-guard-safe)
__device__ float g_qkv[(size_t)Bdim * Sdim * H3];            // 50 MB: [b,s, 3*512]
__device__ float g_scores[(size_t)Bdim * NH * Sdim * Sdim];  // 537 MB: [b,h,q,k]
__device__ float g_ctx[(size_t)Bdim * Sdim * Hdim];          // 17 MB

// ---- packed f32x2 helpers ------------------------------------------------
__device__ __forceinline__ void fma2(ull& d, ull a, ull b) {
    asm("fma.rn.f32x2 %0, %1, %2, %0;" : "+l"(d) : "l"(a), "l"(b));
}
__device__ __forceinline__ ull dup2(float v) {
    ull r;
    asm("mov.b64 %0, {%1, %1};" : "=l"(r) : "f"(v));
    return r;
}
__device__ __forceinline__ float2 unpk(ull v) {
    float2 r;
    asm("mov.b64 {%0, %1}, %2;" : "=f"(r.x), "=f"(r.y) : "l"(v));
    return r;
}

// ---------------------------------------------------------------------------
// Generic C[M,N] = A[M,K] @ B[N,K]^T + bias[N]   (row-major)
// 128x64 block tile, K-chunk 16, 256 threads, 8(M,packed)x4(N) microtile.
// ---------------------------------------------------------------------------
__global__ void __launch_bounds__(256) gemm_abT_kernel(
    const float* __restrict__ A, const float* __restrict__ B,
    const float* __restrict__ bias, float* __restrict__ C,
    int M, int N, int K)
{
    __shared__ __align__(16) float As[16][128];
    __shared__ __align__(16) float Bs[16][64];

    const int tid = threadIdx.x;
    const int tx = tid & 15, ty = tid >> 4;
    const int m0 = blockIdx.y * 128;
    const int n0 = blockIdx.x * 64;

    const int arow = tid & 127, ahalf = tid >> 7;
    const int brow = tid >> 2,  bq    = tid & 3;

    ull acc[4][4];
#pragma unroll
    for (int i = 0; i < 4; i++)
#pragma unroll
        for (int j = 0; j < 4; j++) acc[i][j] = 0ull;

    for (int kc = 0; kc < K; kc += 16) {
#pragma unroll
        for (int p = 0; p < 2; p++) {
            int koff = (ahalf * 2 + p) * 4;
            float4 v = *(const float4*)&A[(size_t)(m0 + arow) * K + kc + koff];
            As[koff + 0][arow] = v.x; As[koff + 1][arow] = v.y;
            As[koff + 2][arow] = v.z; As[koff + 3][arow] = v.w;
        }
        {
            float4 v = *(const float4*)&B[(size_t)(n0 + brow) * K + kc + bq * 4];
            Bs[bq * 4 + 0][brow] = v.x; Bs[bq * 4 + 1][brow] = v.y;
            Bs[bq * 4 + 2][brow] = v.z; Bs[bq * 4 + 3][brow] = v.w;
        }
        __syncthreads();
#pragma unroll
        for (int kk = 0; kk < 16; kk++) {
            float4 b4 = *(const float4*)&Bs[kk][tx * 4];
            ull bb[4] = {dup2(b4.x), dup2(b4.y), dup2(b4.z), dup2(b4.w)};
            const ull* ap = (const ull*)&As[kk][ty * 8];
            ull a0 = ap[0], a1 = ap[1], a2 = ap[2], a3 = ap[3];
#pragma unroll
            for (int j = 0; j < 4; j++) {
                fma2(acc[0][j], a0, bb[j]);
                fma2(acc[1][j], a1, bb[j]);
                fma2(acc[2][j], a2, bb[j]);
                fma2(acc[3][j], a3, bb[j]);
            }
        }
        __syncthreads();
    }

    const int nb = n0 + tx * 4;
    float4 bvec = *(const float4*)&bias[nb];
#pragma unroll
    for (int i = 0; i < 4; i++) {
        float2 c0 = unpk(acc[i][0]), c1 = unpk(acc[i][1]);
        float2 c2 = unpk(acc[i][2]), c3 = unpk(acc[i][3]);
        int m = m0 + ty * 8 + 2 * i;
        float4 olo = {c0.x + bvec.x, c1.x + bvec.y, c2.x + bvec.z, c3.x + bvec.w};
        float4 ohi = {c0.y + bvec.x, c1.y + bvec.y, c2.y + bvec.z, c3.y + bvec.w};
        *(float4*)&C[(size_t)m * N + nb] = olo;
        *(float4*)&C[(size_t)(m + 1) * N + nb] = ohi;
    }
}

// ---------------------------------------------------------------------------
// Scores: S[b,h,q,k] = 0.125*(q.k - dist2(q,k)) ; masked -> -1e30
// 128(q) x 64(k) tile, K-chunk 16, 8x4 packed microtile.
// ---------------------------------------------------------------------------
__global__ void __launch_bounds__(256) scores_kernel(
    const float* __restrict__ pos, const int* __restrict__ mask)
{
    const int bh = blockIdx.z;
    const int b = bh >> 3, h = bh & 7;
    const int q0 = blockIdx.y * 128, k0 = blockIdx.x * 64;

    __shared__ __align__(16) float As[16][128];
    __shared__ __align__(16) float Bs[16][64];
    __shared__ float Pq[128][3], Pk[64][3];
    __shared__ int   Mk[64];

    const int tid = threadIdx.x;
    const int tx = tid & 15, ty = tid >> 4;
    const int arow = tid & 127, ahalf = tid >> 7;
    const int brow = tid >> 2,  bq    = tid & 3;

    if (tid < 128) {
        Pq[tid][0] = pos[(size_t)(b * Sdim + q0 + tid) * 3 + 0];
        Pq[tid][1] = pos[(size_t)(b * Sdim + q0 + tid) * 3 + 1];
        Pq[tid][2] = pos[(size_t)(b * Sdim + q0 + tid) * 3 + 2];
    }
    if (tid < 64) {
        Pk[tid][0] = pos[(size_t)(b * Sdim + k0 + tid) * 3 + 0];
        Pk[tid][1] = pos[(size_t)(b * Sdim + k0 + tid) * 3 + 1];
        Pk[tid][2] = pos[(size_t)(b * Sdim + k0 + tid) * 3 + 2];
        Mk[tid]    = mask[b * Sdim + k0 + tid];
    }

    const float* qbase = g_qkv + (size_t)(b * Sdim + q0) * H3 + h * HD;
    const float* kbase = g_qkv + (size_t)(b * Sdim + k0) * H3 + 512 + h * HD;

    ull acc[4][4];
#pragma unroll
    for (int i = 0; i < 4; i++)
#pragma unroll
        for (int j = 0; j < 4; j++) acc[i][j] = 0ull;

    for (int kc = 0; kc < HD; kc += 16) {
#pragma unroll
        for (int p = 0; p < 2; p++) {
            int koff = (ahalf * 2 + p) * 4;
            float4 v = *(const float4*)&qbase[(size_t)arow * H3 + kc + koff];
            As[koff + 0][arow] = v.x; As[koff + 1][arow] = v.y;
            As[koff + 2][arow] = v.z; As[koff + 3][arow] = v.w;
        }
        {
            float4 v = *(const float4*)&kbase[(size_t)brow * H3 + kc + bq * 4];
            Bs[bq * 4 + 0][brow] = v.x; Bs[bq * 4 + 1][brow] = v.y;
            Bs[bq * 4 + 2][brow] = v.z; Bs[bq * 4 + 3][brow] = v.w;
        }
        __syncthreads();
#pragma unroll
        for (int kk = 0; kk < 16; kk++) {
            float4 b4 = *(const float4*)&Bs[kk][tx * 4];
            ull bb[4] = {dup2(b4.x), dup2(b4.y), dup2(b4.z), dup2(b4.w)};
            const ull* ap = (const ull*)&As[kk][ty * 8];
            ull a0 = ap[0], a1 = ap[1], a2 = ap[2], a3 = ap[3];
#pragma unroll
            for (int j = 0; j < 4; j++) {
                fma2(acc[0][j], a0, bb[j]);
                fma2(acc[1][j], a1, bb[j]);
                fma2(acc[2][j], a2, bb[j]);
                fma2(acc[3][j], a3, bb[j]);
            }
        }
        __syncthreads();
    }

    // epilogue: distance bias + mask
    float kx[4], ky[4], kz[4];
    int   km[4];
#pragma unroll
    for (int j = 0; j < 4; j++) {
        int kk = tx * 4 + j;
        kx[j] = Pk[kk][0]; ky[j] = Pk[kk][1]; kz[j] = Pk[kk][2];
        km[j] = Mk[kk];
    }
#pragma unroll
    for (int i = 0; i < 4; i++) {
        float2 c[4];
#pragma unroll
        for (int j = 0; j < 4; j++) c[j] = unpk(acc[i][j]);
#pragma unroll
        for (int p = 0; p < 2; p++) {
            int ml = ty * 8 + 2 * i + p;
            int q = q0 + ml;
            float px = Pq[ml][0], py = Pq[ml][1], pz = Pq[ml][2];
            float o[4];
#pragma unroll
            for (int j = 0; j < 4; j++) {
                float dx = px - kx[j], dy = py - ky[j], dz = pz - kz[j];
                float d2 = dx * dx + dy * dy + dz * dz;
                float raw = p ? c[j].y : c[j].x;
                float s = 0.125f * (raw - d2);
                o[j] = (km[j] == 0) ? -1e30f : s;
            }
            float4 ov = {o[0], o[1], o[2], o[3]};
            *(float4*)&g_scores[((size_t)bh * Sdim + q) * Sdim + k0 + tx * 4] = ov;
        }
    }
}

// ---------------------------------------------------------------------------
// Softmax in place (all 8 heads of one (b,q)) + head-mean write.
// ---------------------------------------------------------------------------
__global__ void __launch_bounds__(256) softmax_mean_kernel(float* __restrict__ mean_out)
{
    const int bq = blockIdx.x;
    const int b = bq >> 11, q = bq & 2047;
    const int tid = threadIdx.x;
    const int lane = tid & 31, wid = tid >> 5;
    const int kbase = tid * 8;

    __shared__ float red[8];

    float macc[8];
#pragma unroll
    for (int j = 0; j < 8; j++) macc[j] = 0.f;

    for (int h = 0; h < NH; h++) {
        float* row = g_scores + ((size_t)((b * NH + h) * Sdim + q)) * Sdim;
        float4 v0 = *(const float4*)&row[kbase];
        float4 v1 = *(const float4*)&row[kbase + 4];
        float v[8] = {v0.x, v0.y, v0.z, v0.w, v1.x, v1.y, v1.z, v1.w};

        float m = v[0];
#pragma unroll
        for (int j = 1; j < 8; j++) m = fmaxf(m, v[j]);
#pragma unroll
        for (int off = 16; off > 0; off >>= 1)
            m = fmaxf(m, __shfl_xor_sync(0xffffffffu, m, off));
        if (lane == 0) red[wid] = m;
        __syncthreads();
        m = red[0];
#pragma unroll
        for (int w = 1; w < 8; w++) m = fmaxf(m, red[w]);
        __syncthreads();

        float e[8];
        float s = 0.f;
#pragma unroll
        for (int j = 0; j < 8; j++) { e[j] = __expf(v[j] - m); s += e[j]; }
#pragma unroll
        for (int off = 16; off > 0; off >>= 1)
            s += __shfl_xor_sync(0xffffffffu, s, off);
        if (lane == 0) red[wid] = s;
        __syncthreads();
        s = red[0];
#pragma unroll
        for (int w = 1; w < 8; w++) s += red[w];

        float inv = 1.0f / s;
        float wv[8];
#pragma unroll
        for (int j = 0; j < 8; j++) { wv[j] = e[j] * inv; macc[j] += wv[j]; }
        float4 o0 = {wv[0], wv[1], wv[2], wv[3]};
        float4 o1 = {wv[4], wv[5], wv[6], wv[7]};
        *(float4*)&row[kbase] = o0;
        *(float4*)&row[kbase + 4] = o1;
        __syncthreads();
    }

    float* mrow = mean_out + ((size_t)(b * Sdim + q)) * Sdim + kbase;
    float4 m0 = {macc[0] * 0.125f, macc[1] * 0.125f, macc[2] * 0.125f, macc[3] * 0.125f};
    float4 m1 = {macc[4] * 0.125f, macc[5] * 0.125f, macc[6] * 0.125f, macc[7] * 0.125f};
    *(float4*)&mrow[0] = m0;
    *(float4*)&mrow[4] = m1;
}

// ---------------------------------------------------------------------------
// ctx[b,q, h*64+d] = sum_k W[b,h,q,k] * V[b,h,k,d]
// 128(q) x 64(d) tile, K-chunk 16, 8x4 packed microtile.
// ---------------------------------------------------------------------------
__global__ void __launch_bounds__(256) pv_kernel()
{
    const int bh = blockIdx.z;
    const int b = bh >> 3, h = bh & 7;
    const float* A = g_scores + (size_t)bh * Sdim * Sdim;
    const int m0 = blockIdx.x * 128;

    __shared__ __align__(16) float As[16][128];
    __shared__ __align__(16) float Vs[16][64];

    const int tid = threadIdx.x;
    const int tx = tid & 15, ty = tid >> 4;
    const int arow = tid & 127, ahalf = tid >> 7;
    const int vkk = tid >> 4, vfj = tid & 15;

    ull acc[4][4];
#pragma unroll
    for (int i = 0; i < 4; i++)
#pragma unroll
        for (int j = 0; j < 4; j++) acc[i][j] = 0ull;

    const float* vbase = g_qkv + (size_t)(b * Sdim) * H3 + 1024 + h * HD;

    for (int kc = 0; kc < Sdim; kc += 16) {
#pragma unroll
        for (int p = 0; p < 2; p++) {
            int koff = (ahalf * 2 + p) * 4;
            float4 v = *(const float4*)&A[(size_t)(m0 + arow) * Sdim + kc + koff];
            As[koff + 0][arow] = v.x; As[koff + 1][arow] = v.y;
            As[koff + 2][arow] = v.z; As[koff + 3][arow] = v.w;
        }
        {
            float4 v = *(const float4*)&vbase[(size_t)(kc + vkk) * H3 + vfj * 4];
            *(float4*)&Vs[vkk][vfj * 4] = v;
        }
        __syncthreads();
#pragma unroll
        for (int kk = 0; kk < 16; kk++) {
            float4 b4 = *(const float4*)&Vs[kk][tx * 4];
            ull bb[4] = {dup2(b4.x), dup2(b4.y), dup2(b4.z), dup2(b4.w)};
            const ull* ap = (const ull*)&As[kk][ty * 8];
            ull a0 = ap[0], a1 = ap[1], a2 = ap[2], a3 = ap[3];
#pragma unroll
            for (int j = 0; j < 4; j++) {
                fma2(acc[0][j], a0, bb[j]);
                fma2(acc[1][j], a1, bb[j]);
                fma2(acc[2][j], a2, bb[j]);
                fma2(acc[3][j], a3, bb[j]);
            }
        }
        __syncthreads();
    }

#pragma unroll
    for (int i = 0; i < 4; i++) {
        float2 c0 = unpk(acc[i][0]), c1 = unpk(acc[i][1]);
        float2 c2 = unpk(acc[i][2]), c3 = unpk(acc[i][3]);
        int m = m0 + ty * 8 + 2 * i;
        float4 olo = {c0.x, c1.x, c2.x, c3.x};
        float4 ohi = {c0.y, c1.y, c2.y, c3.y};
        *(float4*)&g_ctx[(size_t)(b * Sdim + m) * Hdim + h * HD + tx * 4] = olo;
        *(float4*)&g_ctx[(size_t)(b * Sdim + m + 1) * Hdim + h * HD + tx * 4] = ohi;
    }
}

// ---------------------------------------------------------------------------
extern "C" void kernel_launch(void* const* d_in, const int* in_sizes, int n_in,
                              void* d_out, int out_size)
{
    const float* x     = (const float*)d_in[0];
    const float* pos   = (const float*)d_in[1];
    const int*   mask  = (const int*)d_in[2];
    const float* w_qkv = (const float*)d_in[3];
    const float* b_qkv = (const float*)d_in[4];
    const float* w_out = (const float*)d_in[5];
    const float* b_out = (const float*)d_in[6];

    float* out_proj = (float*)d_out;                               // [B,S,H]
    float* mean_out = out_proj + (size_t)Bdim * Sdim * Hdim;       // [B,S,S]

    float *p_qkv, *p_ctx;
    cudaGetSymbolAddress((void**)&p_qkv, g_qkv);
    cudaGetSymbolAddress((void**)&p_ctx, g_ctx);

    // K1: QKV projection  [8192,1536] = x[8192,512] @ w_qkv^T + b_qkv
    {
        dim3 grid(H3 / 64, (Bdim * Sdim) / 128);
        gemm_abT_kernel<<<grid, 256>>>(x, w_qkv, b_qkv, p_qkv,
                                       Bdim * Sdim, H3, Hdim);
    }
    // K2: scores + bias + mask
    {
        dim3 grid(Sdim / 64, Sdim / 128, Bdim * NH);
        scores_kernel<<<grid, 256>>>(pos, mask);
    }
    // K3: softmax (in place) + head-mean
    softmax_mean_kernel<<<Bdim * Sdim, 256>>>(mean_out);

    // K4: ctx = W @ V
    {
        dim3 grid(Sdim / 128, 1, Bdim * NH);
        pv_kernel<<<grid, 256>>>();
    }
    // K5: output projection  [8192,512] = ctx @ w_out^T + b_out
    {
        dim3 grid(Hdim / 64, (Bdim * Sdim) / 128);
        gemm_abT_kernel<<<grid, 256>>>(p_ctx, w_out, b_out, out_proj,
                                       Bdim * Sdim, Hdim, Hdim);
    }
}

// round 3
// speedup vs baseline: 1.3696x; 1.1629x over previous
#include <cuda_runtime.h>
#include <math.h>

#define Bdim 4
#define Sdim 2048
#define Hdim 512
#define NH   8
#define HD   64
#define H3   1536

typedef unsigned long long ull;

// Static scratch (allocation-guard-safe)
__device__ float g_qkv[(size_t)Bdim * Sdim * H3];            // 50 MB: [b,s, 3*512]
__device__ float g_scores[(size_t)Bdim * NH * Sdim * Sdim];  // 537 MB: [b,h,q,k]
__device__ float g_ctx[(size_t)Bdim * Sdim * Hdim];          // 17 MB

// ---- packed f32x2 helpers ------------------------------------------------
__device__ __forceinline__ void fma2(ull& d, ull a, ull b) {
    asm("fma.rn.f32x2 %0, %1, %2, %0;" : "+l"(d) : "l"(a), "l"(b));
}
__device__ __forceinline__ ull dup2(float v) {
    ull r;
    asm("mov.b64 %0, {%1, %1};" : "=l"(r) : "f"(v));
    return r;
}
__device__ __forceinline__ float2 unpk(ull v) {
    float2 r;
    asm("mov.b64 {%0, %1}, %2;" : "=f"(r.x), "=f"(r.y) : "l"(v));
    return r;
}

#define PAD 132   // smem row stride (floats): 16B-aligned, kills 4-way STS conflicts

// ---------------------------------------------------------------------------
// Generic C[M,N] = A[M,K] @ B[N,K]^T + bias[N]   (row-major)
// 128x128 tile, 256 threads, 8(Mpacked)x8(N) microtile, double-buffered K16.
// ---------------------------------------------------------------------------
__global__ void __launch_bounds__(256) gemm_abT_kernel(
    const float* __restrict__ A, const float* __restrict__ B,
    const float* __restrict__ bias, float* __restrict__ C,
    int M, int N, int K)
{
    __shared__ __align__(16) float As[2][16][PAD];
    __shared__ __align__(16) float Bs[2][16][PAD];

    const int tid = threadIdx.x;
    const int tx = tid & 15, ty = tid >> 4;       // n = tx*8, m = ty*8
    const int m0 = blockIdx.y * 128;
    const int n0 = blockIdx.x * 128;
    const int lrow = tid >> 2;                    // 0..63
    const int lkq  = tid & 3;                     // 0..3

    ull acc[4][8];
#pragma unroll
    for (int i = 0; i < 4; i++)
#pragma unroll
        for (int j = 0; j < 8; j++) acc[i][j] = 0ull;

    float4 ra0, ra1, rb0, rb1;
    const int nchunks = K >> 4;

#define G_LDG(kc)                                                                 \
    ra0 = *(const float4*)&A[(size_t)(m0 + lrow)      * K + (kc) + lkq * 4];      \
    ra1 = *(const float4*)&A[(size_t)(m0 + lrow + 64) * K + (kc) + lkq * 4];      \
    rb0 = *(const float4*)&B[(size_t)(n0 + lrow)      * K + (kc) + lkq * 4];      \
    rb1 = *(const float4*)&B[(size_t)(n0 + lrow + 64) * K + (kc) + lkq * 4];

#define G_STS(st)                                                                 \
    As[st][lkq * 4 + 0][lrow] = ra0.x; As[st][lkq * 4 + 1][lrow] = ra0.y;         \
    As[st][lkq * 4 + 2][lrow] = ra0.z; As[st][lkq * 4 + 3][lrow] = ra0.w;         \
    As[st][lkq * 4 + 0][lrow + 64] = ra1.x; As[st][lkq * 4 + 1][lrow + 64] = ra1.y;\
    As[st][lkq * 4 + 2][lrow + 64] = ra1.z; As[st][lkq * 4 + 3][lrow + 64] = ra1.w;\
    Bs[st][lkq * 4 + 0][lrow] = rb0.x; Bs[st][lkq * 4 + 1][lrow] = rb0.y;         \
    Bs[st][lkq * 4 + 2][lrow] = rb0.z; Bs[st][lkq * 4 + 3][lrow] = rb0.w;         \
    Bs[st][lkq * 4 + 0][lrow + 64] = rb1.x; Bs[st][lkq * 4 + 1][lrow + 64] = rb1.y;\
    Bs[st][lkq * 4 + 2][lrow + 64] = rb1.z; Bs[st][lkq * 4 + 3][lrow + 64] = rb1.w;

    G_LDG(0)
    G_STS(0)
    __syncthreads();

    for (int c = 0; c < nchunks; c++) {
        const int st = c & 1;
        if (c + 1 < nchunks) { G_LDG((c + 1) << 4) }
#pragma unroll
        for (int kk = 0; kk < 16; kk++) {
            const ull* ap = (const ull*)&As[st][kk][ty * 8];
            ull a0 = ap[0], a1 = ap[1], a2 = ap[2], a3 = ap[3];
            float4 b0 = *(const float4*)&Bs[st][kk][tx * 8];
            float4 b1 = *(const float4*)&Bs[st][kk][tx * 8 + 4];
            ull bb[8] = {dup2(b0.x), dup2(b0.y), dup2(b0.z), dup2(b0.w),
                         dup2(b1.x), dup2(b1.y), dup2(b1.z), dup2(b1.w)};
#pragma unroll
            for (int j = 0; j < 8; j++) {
                fma2(acc[0][j], a0, bb[j]);
                fma2(acc[1][j], a1, bb[j]);
                fma2(acc[2][j], a2, bb[j]);
                fma2(acc[3][j], a3, bb[j]);
            }
        }
        if (c + 1 < nchunks) { G_STS(st ^ 1) }
        __syncthreads();
    }

    const int nb = n0 + tx * 8;
    float4 bv0 = *(const float4*)&bias[nb];
    float4 bv1 = *(const float4*)&bias[nb + 4];
#pragma unroll
    for (int i = 0; i < 4; i++) {
        float2 c0 = unpk(acc[i][0]), c1 = unpk(acc[i][1]);
        float2 c2 = unpk(acc[i][2]), c3 = unpk(acc[i][3]);
        float2 c4 = unpk(acc[i][4]), c5 = unpk(acc[i][5]);
        float2 c6 = unpk(acc[i][6]), c7 = unpk(acc[i][7]);
        int m = m0 + ty * 8 + 2 * i;
        float4 lo0 = {c0.x + bv0.x, c1.x + bv0.y, c2.x + bv0.z, c3.x + bv0.w};
        float4 lo1 = {c4.x + bv1.x, c5.x + bv1.y, c6.x + bv1.z, c7.x + bv1.w};
        float4 hi0 = {c0.y + bv0.x, c1.y + bv0.y, c2.y + bv0.z, c3.y + bv0.w};
        float4 hi1 = {c4.y + bv1.x, c5.y + bv1.y, c6.y + bv1.z, c7.y + bv1.w};
        *(float4*)&C[(size_t)m * N + nb]           = lo0;
        *(float4*)&C[(size_t)m * N + nb + 4]       = lo1;
        *(float4*)&C[(size_t)(m + 1) * N + nb]     = hi0;
        *(float4*)&C[(size_t)(m + 1) * N + nb + 4] = hi1;
    }
}

// ---------------------------------------------------------------------------
// Scores: S[b,h,q,k] = 0.125*(q.k - dist2(q,k)) ; masked -> -1e30
// 128(q) x 128(k) tile, 256 threads, 8x8 packed microtile, K=64 (4 chunks).
// ---------------------------------------------------------------------------
__global__ void __launch_bounds__(256) scores_kernel(
    const float* __restrict__ pos, const int* __restrict__ mask)
{
    const int bh = blockIdx.z;
    const int b = bh >> 3, h = bh & 7;
    const int q0 = blockIdx.y * 128, k0 = blockIdx.x * 128;

    __shared__ __align__(16) float As[2][16][PAD];
    __shared__ __align__(16) float Bs[2][16][PAD];
    __shared__ float Pq[128][3], Pk[128][3];
    __shared__ int   Mk[128];

    const int tid = threadIdx.x;
    const int tx = tid & 15, ty = tid >> 4;
    const int lrow = tid >> 2, lkq = tid & 3;

    if (tid < 128) {
        Pq[tid][0] = pos[(size_t)(b * Sdim + q0 + tid) * 3 + 0];
        Pq[tid][1] = pos[(size_t)(b * Sdim + q0 + tid) * 3 + 1];
        Pq[tid][2] = pos[(size_t)(b * Sdim + q0 + tid) * 3 + 2];
    } else {
        int t2 = tid - 128;
        Pk[t2][0] = pos[(size_t)(b * Sdim + k0 + t2) * 3 + 0];
        Pk[t2][1] = pos[(size_t)(b * Sdim + k0 + t2) * 3 + 1];
        Pk[t2][2] = pos[(size_t)(b * Sdim + k0 + t2) * 3 + 2];
        Mk[t2]    = mask[b * Sdim + k0 + t2];
    }

    const float* Aq = g_qkv + (size_t)(b * Sdim + q0) * H3 + h * HD;
    const float* Bk = g_qkv + (size_t)(b * Sdim + k0) * H3 + 512 + h * HD;

    ull acc[4][8];
#pragma unroll
    for (int i = 0; i < 4; i++)
#pragma unroll
        for (int j = 0; j < 8; j++) acc[i][j] = 0ull;

    float4 ra0, ra1, rb0, rb1;

#define S_LDG(kc)                                                                    \
    ra0 = *(const float4*)&Aq[(size_t)(lrow)      * H3 + (kc) + lkq * 4];            \
    ra1 = *(const float4*)&Aq[(size_t)(lrow + 64) * H3 + (kc) + lkq * 4];            \
    rb0 = *(const float4*)&Bk[(size_t)(lrow)      * H3 + (kc) + lkq * 4];            \
    rb1 = *(const float4*)&Bk[(size_t)(lrow + 64) * H3 + (kc) + lkq * 4];

    S_LDG(0)
    G_STS(0)
    __syncthreads();

#pragma unroll
    for (int c = 0; c < 4; c++) {
        const int st = c & 1;
        if (c + 1 < 4) { S_LDG((c + 1) << 4) }
#pragma unroll
        for (int kk = 0; kk < 16; kk++) {
            const ull* ap = (const ull*)&As[st][kk][ty * 8];
            ull a0 = ap[0], a1 = ap[1], a2 = ap[2], a3 = ap[3];
            float4 b0 = *(const float4*)&Bs[st][kk][tx * 8];
            float4 b1 = *(const float4*)&Bs[st][kk][tx * 8 + 4];
            ull bb[8] = {dup2(b0.x), dup2(b0.y), dup2(b0.z), dup2(b0.w),
                         dup2(b1.x), dup2(b1.y), dup2(b1.z), dup2(b1.w)};
#pragma unroll
            for (int j = 0; j < 8; j++) {
                fma2(acc[0][j], a0, bb[j]);
                fma2(acc[1][j], a1, bb[j]);
                fma2(acc[2][j], a2, bb[j]);
                fma2(acc[3][j], a3, bb[j]);
            }
        }
        if (c + 1 < 4) { G_STS(st ^ 1) }
        __syncthreads();
    }

    // epilogue: distance bias + mask
    float kx[8], ky[8], kz[8];
    int   km[8];
#pragma unroll
    for (int j = 0; j < 8; j++) {
        int kk = tx * 8 + j;
        kx[j] = Pk[kk][0]; ky[j] = Pk[kk][1]; kz[j] = Pk[kk][2];
        km[j] = Mk[kk];
    }
#pragma unroll
    for (int i = 0; i < 4; i++) {
        float2 c[8];
#pragma unroll
        for (int j = 0; j < 8; j++) c[j] = unpk(acc[i][j]);
#pragma unroll
        for (int p = 0; p < 2; p++) {
            int ml = ty * 8 + 2 * i + p;
            int q = q0 + ml;
            float px = Pq[ml][0], py = Pq[ml][1], pz = Pq[ml][2];
            float o[8];
#pragma unroll
            for (int j = 0; j < 8; j++) {
                float dx = px - kx[j], dy = py - ky[j], dz = pz - kz[j];
                float d2 = dx * dx + dy * dy + dz * dz;
                float raw = p ? c[j].y : c[j].x;
                float s = 0.125f * (raw - d2);
                o[j] = (km[j] == 0) ? -1e30f : s;
            }
            float* orow = &g_scores[((size_t)bh * Sdim + q) * Sdim + k0 + tx * 8];
            float4 ov0 = {o[0], o[1], o[2], o[3]};
            float4 ov1 = {o[4], o[5], o[6], o[7]};
            *(float4*)&orow[0] = ov0;
            *(float4*)&orow[4] = ov1;
        }
    }
}

// ---------------------------------------------------------------------------
// Softmax in place (all 8 heads of one (b,q)) + head-mean write.
// ---------------------------------------------------------------------------
__global__ void __launch_bounds__(256) softmax_mean_kernel(float* __restrict__ mean_out)
{
    const int bq = blockIdx.x;
    const int b = bq >> 11, q = bq & 2047;
    const int tid = threadIdx.x;
    const int lane = tid & 31, wid = tid >> 5;
    const int kbase = tid * 8;

    __shared__ float red[8];

    float macc[8];
#pragma unroll
    for (int j = 0; j < 8; j++) macc[j] = 0.f;

    for (int h = 0; h < NH; h++) {
        float* row = g_scores + ((size_t)((b * NH + h) * Sdim + q)) * Sdim;
        float4 v0 = *(const float4*)&row[kbase];
        float4 v1 = *(const float4*)&row[kbase + 4];
        float v[8] = {v0.x, v0.y, v0.z, v0.w, v1.x, v1.y, v1.z, v1.w};

        float m = v[0];
#pragma unroll
        for (int j = 1; j < 8; j++) m = fmaxf(m, v[j]);
#pragma unroll
        for (int off = 16; off > 0; off >>= 1)
            m = fmaxf(m, __shfl_xor_sync(0xffffffffu, m, off));
        if (lane == 0) red[wid] = m;
        __syncthreads();
        m = red[0];
#pragma unroll
        for (int w = 1; w < 8; w++) m = fmaxf(m, red[w]);
        __syncthreads();

        float e[8];
        float s = 0.f;
#pragma unroll
        for (int j = 0; j < 8; j++) { e[j] = __expf(v[j] - m); s += e[j]; }
#pragma unroll
        for (int off = 16; off > 0; off >>= 1)
            s += __shfl_xor_sync(0xffffffffu, s, off);
        if (lane == 0) red[wid] = s;
        __syncthreads();
        s = red[0];
#pragma unroll
        for (int w = 1; w < 8; w++) s += red[w];

        float inv = 1.0f / s;
        float wv[8];
#pragma unroll
        for (int j = 0; j < 8; j++) { wv[j] = e[j] * inv; macc[j] += wv[j]; }
        float4 o0 = {wv[0], wv[1], wv[2], wv[3]};
        float4 o1 = {wv[4], wv[5], wv[6], wv[7]};
        *(float4*)&row[kbase] = o0;
        *(float4*)&row[kbase + 4] = o1;
        __syncthreads();
    }

    float* mrow = mean_out + ((size_t)(b * Sdim + q)) * Sdim + kbase;
    float4 m0 = {macc[0] * 0.125f, macc[1] * 0.125f, macc[2] * 0.125f, macc[3] * 0.125f};
    float4 m1 = {macc[4] * 0.125f, macc[5] * 0.125f, macc[6] * 0.125f, macc[7] * 0.125f};
    *(float4*)&mrow[0] = m0;
    *(float4*)&mrow[4] = m1;
}

// ---------------------------------------------------------------------------
// ctx[b,q, h*64+d] = sum_k W[b,h,q,k] * V[b,h,k,d]
// 128(q) x 64(d) tile, 128 threads, 8x8 packed microtile, double-buffered K16.
// ---------------------------------------------------------------------------
__global__ void __launch_bounds__(128) pv_kernel()
{
    const int bh = blockIdx.y;
    const int b = bh >> 3, h = bh & 7;
    const float* A = g_scores + (size_t)bh * Sdim * Sdim;
    const int m0 = blockIdx.x * 128;

    __shared__ __align__(16) float As[2][16][PAD];
    __shared__ __align__(16) float Vs[2][16][68];

    const int tid = threadIdx.x;
    const int tx = tid & 7, ty = tid >> 3;        // n = tx*8 (of 64), m = ty*8 (of 128)
    const int lrow = tid >> 2, lkq = tid & 3;     // A: lrow 0..31 (+32q), lkq 0..3
    const int vrow = tid >> 4, vcol = tid & 15;   // V: vrow 0..7 (+8), vcol*4

    const float* Vbase = g_qkv + (size_t)(b * Sdim) * H3 + 1024 + h * HD;

    ull acc[4][8];
#pragma unroll
    for (int i = 0; i < 4; i++)
#pragma unroll
        for (int j = 0; j < 8; j++) acc[i][j] = 0ull;

    float4 ra[4], rv0, rv1;

#define P_LDG(kc)                                                                     \
    _Pragma("unroll")                                                                 \
    for (int qq = 0; qq < 4; qq++)                                                    \
        ra[qq] = *(const float4*)&A[(size_t)(m0 + lrow + 32 * qq) * Sdim + (kc) + lkq * 4]; \
    rv0 = *(const float4*)&Vbase[(size_t)((kc) + vrow)     * H3 + vcol * 4];          \
    rv1 = *(const float4*)&Vbase[(size_t)((kc) + vrow + 8) * H3 + vcol * 4];

#define P_STS(st)                                                                     \
    _Pragma("unroll")                                                                 \
    for (int qq = 0; qq < 4; qq++) {                                                  \
        As[st][lkq * 4 + 0][lrow + 32 * qq] = ra[qq].x;                               \
        As[st][lkq * 4 + 1][lrow + 32 * qq] = ra[qq].y;                               \
        As[st][lkq * 4 + 2][lrow + 32 * qq] = ra[qq].z;                               \
        As[st][lkq * 4 + 3][lrow + 32 * qq] = ra[qq].w;                               \
    }                                                                                 \
    *(float4*)&Vs[st][vrow][vcol * 4]     = rv0;                                      \
    *(float4*)&Vs[st][vrow + 8][vcol * 4] = rv1;

    P_LDG(0)
    P_STS(0)
    __syncthreads();

    const int nchunks = Sdim >> 4;  // 128
    for (int c = 0; c < nchunks; c++) {
        const int st = c & 1;
        if (c + 1 < nchunks) { P_LDG((c + 1) << 4) }
#pragma unroll
        for (int kk = 0; kk < 16; kk++) {
            const ull* ap = (const ull*)&As[st][kk][ty * 8];
            ull a0 = ap[0], a1 = ap[1], a2 = ap[2], a3 = ap[3];
            float4 b0 = *(const float4*)&Vs[st][kk][tx * 8];
            float4 b1 = *(const float4*)&Vs[st][kk][tx * 8 + 4];
            ull bb[8] = {dup2(b0.x), dup2(b0.y), dup2(b0.z), dup2(b0.w),
                         dup2(b1.x), dup2(b1.y), dup2(b1.z), dup2(b1.w)};
#pragma unroll
            for (int j = 0; j < 8; j++) {
                fma2(acc[0][j], a0, bb[j]);
                fma2(acc[1][j], a1, bb[j]);
                fma2(acc[2][j], a2, bb[j]);
                fma2(acc[3][j], a3, bb[j]);
            }
        }
        if (c + 1 < nchunks) { P_STS(st ^ 1) }
        __syncthreads();
    }

    const int dcol = h * HD + tx * 8;
#pragma unroll
    for (int i = 0; i < 4; i++) {
        float2 c0 = unpk(acc[i][0]), c1 = unpk(acc[i][1]);
        float2 c2 = unpk(acc[i][2]), c3 = unpk(acc[i][3]);
        float2 c4 = unpk(acc[i][4]), c5 = unpk(acc[i][5]);
        float2 c6 = unpk(acc[i][6]), c7 = unpk(acc[i][7]);
        int m = m0 + ty * 8 + 2 * i;
        float4 lo0 = {c0.x, c1.x, c2.x, c3.x};
        float4 lo1 = {c4.x, c5.x, c6.x, c7.x};
        float4 hi0 = {c0.y, c1.y, c2.y, c3.y};
        float4 hi1 = {c4.y, c5.y, c6.y, c7.y};
        float* r0 = &g_ctx[(size_t)(b * Sdim + m) * Hdim + dcol];
        float* r1 = &g_ctx[(size_t)(b * Sdim + m + 1) * Hdim + dcol];
        *(float4*)&r0[0] = lo0; *(float4*)&r0[4] = lo1;
        *(float4*)&r1[0] = hi0; *(float4*)&r1[4] = hi1;
    }
}

// ---------------------------------------------------------------------------
extern "C" void kernel_launch(void* const* d_in, const int* in_sizes, int n_in,
                              void* d_out, int out_size)
{
    const float* x     = (const float*)d_in[0];
    const float* pos   = (const float*)d_in[1];
    const int*   mask  = (const int*)d_in[2];
    const float* w_qkv = (const float*)d_in[3];
    const float* b_qkv = (const float*)d_in[4];
    const float* w_out = (const float*)d_in[5];
    const float* b_out = (const float*)d_in[6];

    float* out_proj = (float*)d_out;                               // [B,S,H]
    float* mean_out = out_proj + (size_t)Bdim * Sdim * Hdim;       // [B,S,S]

    float *p_qkv, *p_ctx;
    cudaGetSymbolAddress((void**)&p_qkv, g_qkv);
    cudaGetSymbolAddress((void**)&p_ctx, g_ctx);

    // K1: QKV projection  [8192,1536] = x[8192,512] @ w_qkv^T + b_qkv
    {
        dim3 grid(H3 / 128, (Bdim * Sdim) / 128);
        gemm_abT_kernel<<<grid, 256>>>(x, w_qkv, b_qkv, p_qkv,
                                       Bdim * Sdim, H3, Hdim);
    }
    // K2: scores + bias + mask
    {
        dim3 grid(Sdim / 128, Sdim / 128, Bdim * NH);
        scores_kernel<<<grid, 256>>>(pos, mask);
    }
    // K3: softmax (in place) + head-mean
    softmax_mean_kernel<<<Bdim * Sdim, 256>>>(mean_out);

    // K4: ctx = W @ V
    {
        dim3 grid(Sdim / 128, Bdim * NH);
        pv_kernel<<<grid, 128>>>();
    }
    // K5: output projection  [8192,512] = ctx @ w_out^T + b_out
    {
        dim3 grid(Hdim / 128, (Bdim * Sdim) / 128);
        gemm_abT_kernel<<<grid, 256>>>(p_ctx, w_out, b_out, out_proj,
                                       Bdim * Sdim, Hdim, Hdim);
    }
}

// round 5
// speedup vs baseline: 1.8213x; 1.3298x over previous
#include <cuda_runtime.h>
#include <cuda_bf16.h>
#include <math.h>
#include <stdint.h>

#define Bdim 4
#define Sdim 2048
#define Hdim 512
#define NH   8
#define HD   64
#define H3   1536

typedef unsigned long long ull;

// Static scratch (allocation-guard-safe)
__device__ float g_scores[(size_t)Bdim * NH * Sdim * Sdim];  // 537 MB (fp32 scores, then packed bf16 hi/lo weights)
__device__ float g_ctx[(size_t)Bdim * Sdim * Hdim];          // 17 MB
__device__ __nv_bfloat16 g_q_hi[(size_t)Bdim * NH * Sdim * HD];
__device__ __nv_bfloat16 g_q_lo[(size_t)Bdim * NH * Sdim * HD];
__device__ __nv_bfloat16 g_k_hi[(size_t)Bdim * NH * Sdim * HD];
__device__ __nv_bfloat16 g_k_lo[(size_t)Bdim * NH * Sdim * HD];
__device__ __nv_bfloat16 g_v_hi[(size_t)Bdim * Sdim * Hdim];
__device__ __nv_bfloat16 g_v_lo[(size_t)Bdim * Sdim * Hdim];

// ---- packed f32x2 helpers (FFMA2 GEMMs) ------------------------------------
__device__ __forceinline__ void fma2(ull& d, ull a, ull b) {
    asm("fma.rn.f32x2 %0, %1, %2, %0;" : "+l"(d) : "l"(a), "l"(b));
}
__device__ __forceinline__ ull dup2(float v) {
    ull r;
    asm("mov.b64 %0, {%1, %1};" : "=l"(r) : "f"(v));
    return r;
}
__device__ __forceinline__ float2 unpk(ull v) {
    float2 r;
    asm("mov.b64 {%0, %1}, %2;" : "=f"(r.x), "=f"(r.y) : "l"(v));
    return r;
}

// ---- mma.sync / ldmatrix helpers -------------------------------------------
__device__ __forceinline__ uint32_t smem_u32(const void* p) {
    uint32_t a;
    asm("{ .reg .u64 t; cvta.to.shared.u64 t, %1; cvt.u32.u64 %0, t; }" : "=r"(a) : "l"(p));
    return a;
}
__device__ __forceinline__ void ldsm_x4(uint32_t* r, uint32_t addr) {
    asm volatile("ldmatrix.sync.aligned.m8n8.x4.shared.b16 {%0,%1,%2,%3}, [%4];"
                 : "=r"(r[0]), "=r"(r[1]), "=r"(r[2]), "=r"(r[3]) : "r"(addr));
}
__device__ __forceinline__ void ldsm_x2(uint32_t* r, uint32_t addr) {
    asm volatile("ldmatrix.sync.aligned.m8n8.x2.shared.b16 {%0,%1}, [%2];"
                 : "=r"(r[0]), "=r"(r[1]) : "r"(addr));
}
__device__ __forceinline__ void ldsm_x2t(uint32_t* r, uint32_t addr) {
    asm volatile("ldmatrix.sync.aligned.m8n8.x2.trans.shared.b16 {%0,%1}, [%2];"
                 : "=r"(r[0]), "=r"(r[1]) : "r"(addr));
}
__device__ __forceinline__ void mma_bf16(float* d, const uint32_t* a, const uint32_t* b) {
    asm volatile("mma.sync.aligned.m16n8k16.row.col.f32.bf16.bf16.f32 "
                 "{%0,%1,%2,%3}, {%4,%5,%6,%7}, {%8,%9}, {%0,%1,%2,%3};"
                 : "+f"(d[0]), "+f"(d[1]), "+f"(d[2]), "+f"(d[3])
                 : "r"(a[0]), "r"(a[1]), "r"(a[2]), "r"(a[3]), "r"(b[0]), "r"(b[1]));
}
__device__ __forceinline__ uint32_t prmtf(uint32_t a, uint32_t b, uint32_t s) {
    uint32_t d;
    asm("prmt.b32 %0, %1, %2, %3;" : "=r"(d) : "r"(a), "r"(b), "r"(s));
    return d;
}
__device__ __forceinline__ uint32_t pack_bf16x2(float e0, float e1) {
    uint32_t r;  // lower half = e0, upper = e1
    asm("cvt.rn.bf16x2.f32 %0, %2, %1;" : "=r"(r) : "f"(e0), "f"(e1));
    return r;
}
// split 8 fp32 -> hi/lo bf16x4 words
__device__ __forceinline__ void split8(const float* v, uint4& hi, uint4& lo) {
    uint32_t hw[4], lw[4];
#pragma unroll
    for (int j = 0; j < 4; j++) {
        float e0 = v[2 * j], e1 = v[2 * j + 1];
        uint32_t h = pack_bf16x2(e0, e1);
        float f0 = __uint_as_float(h << 16);
        float f1 = __uint_as_float(h & 0xffff0000u);
        hw[j] = h;
        lw[j] = pack_bf16x2(e0 - f0, e1 - f1);
    }
    hi = make_uint4(hw[0], hw[1], hw[2], hw[3]);
    lo = make_uint4(lw[0], lw[1], lw[2], lw[3]);
}

#define PAD 132

// ---------------------------------------------------------------------------
// K1: QKV GEMM (FFMA2) + split-bf16 scatter epilogue.
// [8192,1536] = x[8192,512] @ w_qkv^T + b_qkv
// ---------------------------------------------------------------------------
__global__ void __launch_bounds__(256) qkv_gemm_split_kernel(
    const float* __restrict__ A, const float* __restrict__ B,
    const float* __restrict__ bias)
{
    const int M = Bdim * Sdim, N = H3, K = Hdim;
    __shared__ __align__(16) float As[2][16][PAD];
    __shared__ __align__(16) float Bs[2][16][PAD];

    const int tid = threadIdx.x;
    const int tx = tid & 15, ty = tid >> 4;
    const int m0 = blockIdx.y * 128;
    const int n0 = blockIdx.x * 128;
    const int lrow = tid >> 2;
    const int lkq  = tid & 3;
    (void)M;

    ull acc[4][8];
#pragma unroll
    for (int i = 0; i < 4; i++)
#pragma unroll
        for (int j = 0; j < 8; j++) acc[i][j] = 0ull;

    float4 ra0, ra1, rb0, rb1;
    const int nchunks = K >> 4;

#define G_LDG(kc)                                                                 \
    ra0 = *(const float4*)&A[(size_t)(m0 + lrow)      * K + (kc) + lkq * 4];      \
    ra1 = *(const float4*)&A[(size_t)(m0 + lrow + 64) * K + (kc) + lkq * 4];      \
    rb0 = *(const float4*)&B[(size_t)(n0 + lrow)      * K + (kc) + lkq * 4];      \
    rb1 = *(const float4*)&B[(size_t)(n0 + lrow + 64) * K + (kc) + lkq * 4];

#define G_STS(st)                                                                 \
    As[st][lkq * 4 + 0][lrow] = ra0.x; As[st][lkq * 4 + 1][lrow] = ra0.y;         \
    As[st][lkq * 4 + 2][lrow] = ra0.z; As[st][lkq * 4 + 3][lrow] = ra0.w;         \
    As[st][lkq * 4 + 0][lrow + 64] = ra1.x; As[st][lkq * 4 + 1][lrow + 64] = ra1.y;\
    As[st][lkq * 4 + 2][lrow + 64] = ra1.z; As[st][lkq * 4 + 3][lrow + 64] = ra1.w;\
    Bs[st][lkq * 4 + 0][lrow] = rb0.x; Bs[st][lkq * 4 + 1][lrow] = rb0.y;         \
    Bs[st][lkq * 4 + 2][lrow] = rb0.z; Bs[st][lkq * 4 + 3][lrow] = rb0.w;         \
    Bs[st][lkq * 4 + 0][lrow + 64] = rb1.x; Bs[st][lkq * 4 + 1][lrow + 64] = rb1.y;\
    Bs[st][lkq * 4 + 2][lrow + 64] = rb1.z; Bs[st][lkq * 4 + 3][lrow + 64] = rb1.w;

    G_LDG(0)
    G_STS(0)
    __syncthreads();

    for (int c = 0; c < nchunks; c++) {
        const int st = c & 1;
        if (c + 1 < nchunks) { G_LDG((c + 1) << 4) }
#pragma unroll
        for (int kk = 0; kk < 16; kk++) {
            const ull* ap = (const ull*)&As[st][kk][ty * 8];
            ull a0 = ap[0], a1 = ap[1], a2 = ap[2], a3 = ap[3];
            float4 b0 = *(const float4*)&Bs[st][kk][tx * 8];
            float4 b1 = *(const float4*)&Bs[st][kk][tx * 8 + 4];
            ull bb[8] = {dup2(b0.x), dup2(b0.y), dup2(b0.z), dup2(b0.w),
                         dup2(b1.x), dup2(b1.y), dup2(b1.z), dup2(b1.w)};
#pragma unroll
            for (int j = 0; j < 8; j++) {
                fma2(acc[0][j], a0, bb[j]);
                fma2(acc[1][j], a1, bb[j]);
                fma2(acc[2][j], a2, bb[j]);
                fma2(acc[3][j], a3, bb[j]);
            }
        }
        if (c + 1 < nchunks) { G_STS(st ^ 1) }
        __syncthreads();
    }

    const int nb = n0 + tx * 8;
    float bb8[8];
#pragma unroll
    for (int j = 0; j < 8; j++) bb8[j] = bias[nb + j];

    const int region = nb >> 9;          // 0=q, 1=k, 2=v (uniform per block)
    const int head   = (nb >> 6) & 7;
    const int d0     = nb & 63;

#pragma unroll
    for (int i = 0; i < 4; i++) {
        int mbase = m0 + ty * 8 + 2 * i;
#pragma unroll
        for (int p = 0; p < 2; p++) {
            float v[8];
#pragma unroll
            for (int j = 0; j < 8; j++) {
                float2 cj = unpk(acc[i][j]);
                v[j] = (p ? cj.y : cj.x) + bb8[j];
            }
            uint4 hi, lo;
            split8(v, hi, lo);
            int mm = mbase + p;
            int b = mm >> 11, s = mm & 2047;
            if (region == 0) {
                size_t off = ((size_t)(b * NH + head) * Sdim + s) * HD + d0;
                *(uint4*)&g_q_hi[off] = hi;
                *(uint4*)&g_q_lo[off] = lo;
            } else if (region == 1) {
                size_t off = ((size_t)(b * NH + head) * Sdim + s) * HD + d0;
                *(uint4*)&g_k_hi[off] = hi;
                *(uint4*)&g_k_lo[off] = lo;
            } else {
                size_t off = ((size_t)b * Sdim + s) * Hdim + head * HD + d0;
                *(uint4*)&g_v_hi[off] = hi;
                *(uint4*)&g_v_lo[off] = lo;
            }
        }
    }
}

// ---------------------------------------------------------------------------
// K2: scores via mma.sync bf16 (3-term split).
// CTA: 128q x 128k of one (b,h). 8 warps: wm(4) x wn(2); warp = 32q x 64k.
// ---------------------------------------------------------------------------
#define SQS 72                       // smem row stride (bf16 elems) = 144B
#define SC_ARR (128 * SQS)           // per-array elems
#define SC_SMEM (4 * SC_ARR * 2 + 128 * 3 * 4 * 2 + 128 * 4)

__global__ void __launch_bounds__(256) scores_mma_kernel(
    const float* __restrict__ pos, const int* __restrict__ mask)
{
    extern __shared__ __align__(16) char sm[];
    __nv_bfloat16* Qh = (__nv_bfloat16*)sm;
    __nv_bfloat16* Ql = Qh + SC_ARR;
    __nv_bfloat16* Kh = Qh + 2 * SC_ARR;
    __nv_bfloat16* Kl = Qh + 3 * SC_ARR;
    float* Pq = (float*)(sm + 4 * SC_ARR * 2);
    float* Pk = Pq + 128 * 3;
    int*   Mk = (int*)(Pk + 128 * 3);

    const int tid = threadIdx.x, lane = tid & 31, wid = tid >> 5;
    const int bh = blockIdx.z, b = bh >> 3;
    const int q0 = blockIdx.y * 128, k0 = blockIdx.x * 128;

    const __nv_bfloat16* sQh = g_q_hi + ((size_t)bh * Sdim + q0) * HD;
    const __nv_bfloat16* sQl = g_q_lo + ((size_t)bh * Sdim + q0) * HD;
    const __nv_bfloat16* sKh = g_k_hi + ((size_t)bh * Sdim + k0) * HD;
    const __nv_bfloat16* sKl = g_k_lo + ((size_t)bh * Sdim + k0) * HD;

#pragma unroll
    for (int i = 0; i < 4; i++) {
        int idx = tid + 256 * i;
        int r = idx >> 3, c = idx & 7;
        *(uint4*)&Qh[r * SQS + c * 8] = *(const uint4*)&sQh[(size_t)r * HD + c * 8];
        *(uint4*)&Ql[r * SQS + c * 8] = *(const uint4*)&sQl[(size_t)r * HD + c * 8];
        *(uint4*)&Kh[r * SQS + c * 8] = *(const uint4*)&sKh[(size_t)r * HD + c * 8];
        *(uint4*)&Kl[r * SQS + c * 8] = *(const uint4*)&sKl[(size_t)r * HD + c * 8];
    }
    if (tid < 128) {
        Pq[tid * 3 + 0] = pos[(size_t)(b * Sdim + q0 + tid) * 3 + 0];
        Pq[tid * 3 + 1] = pos[(size_t)(b * Sdim + q0 + tid) * 3 + 1];
        Pq[tid * 3 + 2] = pos[(size_t)(b * Sdim + q0 + tid) * 3 + 2];
    } else {
        int t2 = tid - 128;
        Pk[t2 * 3 + 0] = pos[(size_t)(b * Sdim + k0 + t2) * 3 + 0];
        Pk[t2 * 3 + 1] = pos[(size_t)(b * Sdim + k0 + t2) * 3 + 1];
        Pk[t2 * 3 + 2] = pos[(size_t)(b * Sdim + k0 + t2) * 3 + 2];
        Mk[t2]         = mask[b * Sdim + k0 + t2];
    }
    __syncthreads();

    const int wm = wid & 3, wn = wid >> 2;
    const uint32_t qb = smem_u32(Qh);
    const uint32_t kb = smem_u32(Kh);
    const uint32_t LOFF = SC_ARR * 2;  // bytes hi->lo

    float d[2][8][4];
#pragma unroll
    for (int mt = 0; mt < 2; mt++)
#pragma unroll
        for (int nt = 0; nt < 8; nt++)
#pragma unroll
            for (int e = 0; e < 4; e++) d[mt][nt][e] = 0.f;

#pragma unroll
    for (int ks = 0; ks < 4; ks++) {
        uint32_t ah[2][4], al[2][4];
#pragma unroll
        for (int mt = 0; mt < 2; mt++) {
            int row = wm * 32 + mt * 16 + (lane & 7) + ((lane >> 3) & 1) * 8;
            int col = ks * 16 + (lane >> 4) * 8;
            uint32_t adr = qb + (row * SQS + col) * 2;
            ldsm_x4(ah[mt], adr);
            ldsm_x4(al[mt], adr + LOFF);
        }
        uint32_t bhf[8][2], blf[8][2];
#pragma unroll
        for (int nt = 0; nt < 8; nt++) {
            int row = wn * 64 + nt * 8 + (lane & 7);
            int col = ks * 16 + ((lane >> 3) & 1) * 8;
            uint32_t adr = kb + (row * SQS + col) * 2;
            ldsm_x2(bhf[nt], adr);
            ldsm_x2(blf[nt], adr + LOFF);
        }
#pragma unroll
        for (int mt = 0; mt < 2; mt++)
#pragma unroll
            for (int nt = 0; nt < 8; nt++) {
                mma_bf16(d[mt][nt], ah[mt], bhf[nt]);
                mma_bf16(d[mt][nt], ah[mt], blf[nt]);
                mma_bf16(d[mt][nt], al[mt], bhf[nt]);
            }
    }

    // epilogue: 0.125*(qk - dist2), mask
    const int g = lane >> 2, tig = lane & 3;
#pragma unroll
    for (int mt = 0; mt < 2; mt++) {
#pragma unroll
        for (int hf = 0; hf < 2; hf++) {
            int lr = wm * 32 + mt * 16 + g + hf * 8;
            float px = Pq[lr * 3 + 0], py = Pq[lr * 3 + 1], pz = Pq[lr * 3 + 2];
            float* orow = &g_scores[((size_t)bh * Sdim + q0 + lr) * Sdim + k0];
#pragma unroll
            for (int nt = 0; nt < 8; nt++) {
                int lc = wn * 64 + nt * 8 + tig * 2;
                float v0 = d[mt][nt][hf * 2 + 0];
                float v1 = d[mt][nt][hf * 2 + 1];
                float dx0 = px - Pk[lc * 3 + 0], dy0 = py - Pk[lc * 3 + 1], dz0 = pz - Pk[lc * 3 + 2];
                float dx1 = px - Pk[lc * 3 + 3], dy1 = py - Pk[lc * 3 + 4], dz1 = pz - Pk[lc * 3 + 5];
                float s0 = 0.125f * (v0 - (dx0 * dx0 + dy0 * dy0 + dz0 * dz0));
                float s1 = 0.125f * (v1 - (dx1 * dx1 + dy1 * dy1 + dz1 * dz1));
                if (Mk[lc] == 0)     s0 = -1e30f;
                if (Mk[lc + 1] == 0) s1 = -1e30f;
                float2 o = {s0, s1};
                *(float2*)&orow[lc] = o;
            }
        }
    }
}

// ---------------------------------------------------------------------------
// K3: softmax in place + head-mean; writes weights packed (bf16 hi<<16 | lo).
// ---------------------------------------------------------------------------
__global__ void __launch_bounds__(256) softmax_mean_kernel(float* __restrict__ mean_out)
{
    const int bq = blockIdx.x;
    const int b = bq >> 11, q = bq & 2047;
    const int tid = threadIdx.x;
    const int lane = tid & 31, wid = tid >> 5;
    const int kbase = tid * 8;

    __shared__ float red[8];

    float macc[8];
#pragma unroll
    for (int j = 0; j < 8; j++) macc[j] = 0.f;

    for (int h = 0; h < NH; h++) {
        float* row = g_scores + ((size_t)((b * NH + h) * Sdim + q)) * Sdim;
        float4 v0 = *(const float4*)&row[kbase];
        float4 v1 = *(const float4*)&row[kbase + 4];
        float v[8] = {v0.x, v0.y, v0.z, v0.w, v1.x, v1.y, v1.z, v1.w};

        float m = v[0];
#pragma unroll
        for (int j = 1; j < 8; j++) m = fmaxf(m, v[j]);
#pragma unroll
        for (int off = 16; off > 0; off >>= 1)
            m = fmaxf(m, __shfl_xor_sync(0xffffffffu, m, off));
        if (lane == 0) red[wid] = m;
        __syncthreads();
        m = red[0];
#pragma unroll
        for (int w = 1; w < 8; w++) m = fmaxf(m, red[w]);
        __syncthreads();

        float e[8];
        float s = 0.f;
#pragma unroll
        for (int j = 0; j < 8; j++) { e[j] = __expf(v[j] - m); s += e[j]; }
#pragma unroll
        for (int off = 16; off > 0; off >>= 1)
            s += __shfl_xor_sync(0xffffffffu, s, off);
        if (lane == 0) red[wid] = s;
        __syncthreads();
        s = red[0];
#pragma unroll
        for (int w = 1; w < 8; w++) s += red[w];

        float inv = 1.0f / s;
        uint32_t pw[8];
#pragma unroll
        for (int j = 0; j < 8; j++) {
            float w = e[j] * inv;
            macc[j] += w;
            uint32_t u = __float_as_uint(w);
            uint32_t hi16 = (u + 0x7fffu + ((u >> 16) & 1u)) >> 16;
            float r = w - __uint_as_float(hi16 << 16);
            uint32_t u2 = __float_as_uint(r);
            uint32_t lo16 = (u2 + 0x7fffu + ((u2 >> 16) & 1u)) >> 16;
            pw[j] = (hi16 << 16) | lo16;
        }
        uint32_t* prow = (uint32_t*)row;
        *(uint4*)&prow[kbase]     = make_uint4(pw[0], pw[1], pw[2], pw[3]);
        *(uint4*)&prow[kbase + 4] = make_uint4(pw[4], pw[5], pw[6], pw[7]);
        __syncthreads();
    }

    float* mrow = mean_out + ((size_t)(b * Sdim + q)) * Sdim + kbase;
    float4 m0 = {macc[0] * 0.125f, macc[1] * 0.125f, macc[2] * 0.125f, macc[3] * 0.125f};
    float4 m1 = {macc[4] * 0.125f, macc[5] * 0.125f, macc[6] * 0.125f, macc[7] * 0.125f};
    *(float4*)&mrow[0] = m0;
    *(float4*)&mrow[4] = m1;
}

// ---------------------------------------------------------------------------
// K4: pv via mma.sync bf16 (3-term): ctx[128q x 64d] = W @ V per (b,h).
// kseq chunks of 64, double-buffered smem. W read packed, split via PRMT.
// ---------------------------------------------------------------------------
#define PVS 72
#define PV_STAGE (2 * 128 * PVS + 2 * 64 * PVS)  // 27648 bf16 elems
#define PV_WL  (128 * PVS)                        // 9216
#define PV_VH  (2 * 128 * PVS)                    // 18432
#define PV_VL  (PV_VH + 64 * PVS)                 // 23040
#define PV_SMEM_B (2 * PV_STAGE * 2)              // 110592 bytes

__global__ void __launch_bounds__(256) pv_mma_kernel()
{
    extern __shared__ __align__(16) char sm[];
    __nv_bfloat16* Sb = (__nv_bfloat16*)sm;

    const int tid = threadIdx.x, lane = tid & 31, wid = tid >> 5;
    const int bh = blockIdx.y, b = bh >> 3, h = bh & 7;
    const int q0 = blockIdx.x * 128;

    const uint32_t* Wp = (const uint32_t*)g_scores + (size_t)bh * Sdim * Sdim + (size_t)q0 * Sdim;
    const __nv_bfloat16* Vh_src = g_v_hi + (size_t)b * Sdim * Hdim + h * HD;
    const __nv_bfloat16* Vl_src = g_v_lo + (size_t)b * Sdim * Hdim + h * HD;

    const int wm = wid & 3, wn = wid >> 2;

    float d[2][4][4];
#pragma unroll
    for (int mt = 0; mt < 2; mt++)
#pragma unroll
        for (int nt = 0; nt < 4; nt++)
#pragma unroll
            for (int e = 0; e < 4; e++) d[mt][nt][e] = 0.f;

    uint4 rw[8], rvh[2], rvl[2];

#define PV_LDG(kc)                                                                \
    _Pragma("unroll") for (int i = 0; i < 8; i++) {                               \
        int idx = tid + 256 * i; int r = idx >> 4, cc = idx & 15;                 \
        rw[i] = *(const uint4*)&Wp[(size_t)r * Sdim + (kc) + cc * 4];             \
    }                                                                             \
    _Pragma("unroll") for (int i = 0; i < 2; i++) {                               \
        int idx = tid + 256 * i; int kk = idx >> 3, c8 = idx & 7;                 \
        rvh[i] = *(const uint4*)&Vh_src[(size_t)((kc) + kk) * Hdim + c8 * 8];     \
        rvl[i] = *(const uint4*)&Vl_src[(size_t)((kc) + kk) * Hdim + c8 * 8];     \
    }

#define PV_STS(st) {                                                              \
    __nv_bfloat16* Wh = Sb + (st) * PV_STAGE;                                     \
    __nv_bfloat16* Wl = Wh + PV_WL;                                               \
    __nv_bfloat16* Vh = Sb + (st) * PV_STAGE + PV_VH;                             \
    __nv_bfloat16* Vl = Sb + (st) * PV_STAGE + PV_VL;                             \
    _Pragma("unroll") for (int i = 0; i < 8; i++) {                               \
        int idx = tid + 256 * i; int r = idx >> 4, cc = idx & 15;                 \
        uint32_t h01 = prmtf(rw[i].x, rw[i].y, 0x7632u);                          \
        uint32_t h23 = prmtf(rw[i].z, rw[i].w, 0x7632u);                          \
        uint32_t l01 = prmtf(rw[i].x, rw[i].y, 0x5410u);                          \
        uint32_t l23 = prmtf(rw[i].z, rw[i].w, 0x5410u);                          \
        *(uint2*)&Wh[r * PVS + cc * 4] = make_uint2(h01, h23);                    \
        *(uint2*)&Wl[r * PVS + cc * 4] = make_uint2(l01, l23);                    \
    }                                                                             \
    _Pragma("unroll") for (int i = 0; i < 2; i++) {                               \
        int idx = tid + 256 * i; int kk = idx >> 3, c8 = idx & 7;                 \
        *(uint4*)&Vh[kk * PVS + c8 * 8] = rvh[i];                                 \
        *(uint4*)&Vl[kk * PVS + c8 * 8] = rvl[i];                                 \
    }}

    PV_LDG(0)
    PV_STS(0)
    __syncthreads();

    for (int c = 0; c < 32; c++) {
        const int st = c & 1;
        if (c < 31) { PV_LDG((c + 1) * 64) }
        {
            uint32_t wb = smem_u32(Sb + st * PV_STAGE);
            const uint32_t WLOFF = PV_WL * 2;
            const uint32_t VHB   = PV_VH * 2;
            const uint32_t VLOFF = (PV_VL - PV_VH) * 2;
#pragma unroll
            for (int ks = 0; ks < 4; ks++) {
                uint32_t ah[2][4], al[2][4];
#pragma unroll
                for (int mt = 0; mt < 2; mt++) {
                    int row = wm * 32 + mt * 16 + (lane & 7) + ((lane >> 3) & 1) * 8;
                    int col = ks * 16 + (lane >> 4) * 8;
                    uint32_t adr = wb + (row * PVS + col) * 2;
                    ldsm_x4(ah[mt], adr);
                    ldsm_x4(al[mt], adr + WLOFF);
                }
                uint32_t bhf[4][2], blf[4][2];
#pragma unroll
                for (int nt = 0; nt < 4; nt++) {
                    int row = ks * 16 + (lane & 7) + ((lane >> 3) & 1) * 8;
                    int col = wn * 32 + nt * 8;
                    uint32_t adr = wb + VHB + (row * PVS + col) * 2;
                    ldsm_x2t(bhf[nt], adr);
                    ldsm_x2t(blf[nt], adr + VLOFF);
                }
#pragma unroll
                for (int mt = 0; mt < 2; mt++)
#pragma unroll
                    for (int nt = 0; nt < 4; nt++) {
                        mma_bf16(d[mt][nt], ah[mt], bhf[nt]);
                        mma_bf16(d[mt][nt], ah[mt], blf[nt]);
                        mma_bf16(d[mt][nt], al[mt], bhf[nt]);
                    }
            }
        }
        __syncthreads();
        if (c < 31) {
            PV_STS(st ^ 1)
            __syncthreads();
        }
    }

    const int g = lane >> 2, tig = lane & 3;
#pragma unroll
    for (int mt = 0; mt < 2; mt++)
#pragma unroll
        for (int nt = 0; nt < 4; nt++)
#pragma unroll
            for (int hf = 0; hf < 2; hf++) {
                int r = q0 + wm * 32 + mt * 16 + g + hf * 8;
                int col = h * HD + wn * 32 + nt * 8 + tig * 2;
                float2 o = {d[mt][nt][hf * 2 + 0], d[mt][nt][hf * 2 + 1]};
                *(float2*)&g_ctx[(size_t)(b * Sdim + r) * Hdim + col] = o;
            }
}

// ---------------------------------------------------------------------------
// K5: generic C = A @ B^T + bias (FFMA2, unchanged)
// ---------------------------------------------------------------------------
__global__ void __launch_bounds__(256) gemm_abT_kernel(
    const float* __restrict__ A, const float* __restrict__ B,
    const float* __restrict__ bias, float* __restrict__ C,
    int M, int N, int K)
{
    __shared__ __align__(16) float As[2][16][PAD];
    __shared__ __align__(16) float Bs[2][16][PAD];

    const int tid = threadIdx.x;
    const int tx = tid & 15, ty = tid >> 4;
    const int m0 = blockIdx.y * 128;
    const int n0 = blockIdx.x * 128;
    const int lrow = tid >> 2;
    const int lkq  = tid & 3;

    ull acc[4][8];
#pragma unroll
    for (int i = 0; i < 4; i++)
#pragma unroll
        for (int j = 0; j < 8; j++) acc[i][j] = 0ull;

    float4 ra0, ra1, rb0, rb1;
    const int nchunks = K >> 4;

    G_LDG(0)
    G_STS(0)
    __syncthreads();

    for (int c = 0; c < nchunks; c++) {
        const int st = c & 1;
        if (c + 1 < nchunks) { G_LDG((c + 1) << 4) }
#pragma unroll
        for (int kk = 0; kk < 16; kk++) {
            const ull* ap = (const ull*)&As[st][kk][ty * 8];
            ull a0 = ap[0], a1 = ap[1], a2 = ap[2], a3 = ap[3];
            float4 b0 = *(const float4*)&Bs[st][kk][tx * 8];
            float4 b1 = *(const float4*)&Bs[st][kk][tx * 8 + 4];
            ull bb[8] = {dup2(b0.x), dup2(b0.y), dup2(b0.z), dup2(b0.w),
                         dup2(b1.x), dup2(b1.y), dup2(b1.z), dup2(b1.w)};
#pragma unroll
            for (int j = 0; j < 8; j++) {
                fma2(acc[0][j], a0, bb[j]);
                fma2(acc[1][j], a1, bb[j]);
                fma2(acc[2][j], a2, bb[j]);
                fma2(acc[3][j], a3, bb[j]);
            }
        }
        if (c + 1 < nchunks) { G_STS(st ^ 1) }
        __syncthreads();
    }

    const int nb = n0 + tx * 8;
    float4 bv0 = *(const float4*)&bias[nb];
    float4 bv1 = *(const float4*)&bias[nb + 4];
#pragma unroll
    for (int i = 0; i < 4; i++) {
        float2 c0 = unpk(acc[i][0]), c1 = unpk(acc[i][1]);
        float2 c2 = unpk(acc[i][2]), c3 = unpk(acc[i][3]);
        float2 c4 = unpk(acc[i][4]), c5 = unpk(acc[i][5]);
        float2 c6 = unpk(acc[i][6]), c7 = unpk(acc[i][7]);
        int m = m0 + ty * 8 + 2 * i;
        float4 lo0 = {c0.x + bv0.x, c1.x + bv0.y, c2.x + bv0.z, c3.x + bv0.w};
        float4 lo1 = {c4.x + bv1.x, c5.x + bv1.y, c6.x + bv1.z, c7.x + bv1.w};
        float4 hi0 = {c0.y + bv0.x, c1.y + bv0.y, c2.y + bv0.z, c3.y + bv0.w};
        float4 hi1 = {c4.y + bv1.x, c5.y + bv1.y, c6.y + bv1.z, c7.y + bv1.w};
        *(float4*)&C[(size_t)m * N + nb]           = lo0;
        *(float4*)&C[(size_t)m * N + nb + 4]       = lo1;
        *(float4*)&C[(size_t)(m + 1) * N + nb]     = hi0;
        *(float4*)&C[(size_t)(m + 1) * N + nb + 4] = hi1;
    }
}

// ---------------------------------------------------------------------------
extern "C" void kernel_launch(void* const* d_in, const int* in_sizes, int n_in,
                              void* d_out, int out_size)
{
    const float* x     = (const float*)d_in[0];
    const float* pos   = (const float*)d_in[1];
    const int*   mask  = (const int*)d_in[2];
    const float* w_qkv = (const float*)d_in[3];
    const float* b_qkv = (const float*)d_in[4];
    const float* w_out = (const float*)d_in[5];
    const float* b_out = (const float*)d_in[6];

    float* out_proj = (float*)d_out;
    float* mean_out = out_proj + (size_t)Bdim * Sdim * Hdim;

    float* p_ctx;
    cudaGetSymbolAddress((void**)&p_ctx, g_ctx);

    cudaFuncSetAttribute(scores_mma_kernel, cudaFuncAttributeMaxDynamicSharedMemorySize, SC_SMEM);
    cudaFuncSetAttribute(pv_mma_kernel, cudaFuncAttributeMaxDynamicSharedMemorySize, PV_SMEM_B);

    // K1: QKV projection + split
    {
        dim3 grid(H3 / 128, (Bdim * Sdim) / 128);
        qkv_gemm_split_kernel<<<grid, 256>>>(x, w_qkv, b_qkv);
    }
    // K2: scores (tensor)
    {
        dim3 grid(Sdim / 128, Sdim / 128, Bdim * NH);
        scores_mma_kernel<<<grid, 256, SC_SMEM>>>(pos, mask);
    }
    // K3: softmax + pack + head-mean
    softmax_mean_kernel<<<Bdim * Sdim, 256>>>(mean_out);

    // K4: ctx = W @ V (tensor)
    {
        dim3 grid(Sdim / 128, Bdim * NH);
        pv_mma_kernel<<<grid, 256, PV_SMEM_B>>>();
    }
    // K5: output projection
    {
        dim3 grid(Hdim / 128, (Bdim * Sdim) / 128);
        gemm_abT_kernel<<<grid, 256>>>(p_ctx, w_out, b_out, out_proj,
                                       Bdim * Sdim, Hdim, Hdim);
    }
}

// round 6
// speedup vs baseline: 1.9906x; 1.0930x over previous
#include <cuda_runtime.h>
#include <cuda_bf16.h>
#include <math.h>
#include <stdint.h>

#define Bdim 4
#define Sdim 2048
#define Hdim 512
#define NH   8
#define HD   64
#define H3   1536

typedef unsigned long long ull;

// Static scratch (allocation-guard-safe)
__device__ float g_scores[(size_t)Bdim * NH * Sdim * Sdim];  // 537 MB fp32 scores (read-only after K2)
__device__ float g_ctx[(size_t)Bdim * Sdim * Hdim];          // 17 MB
__device__ float2 g_stats[(size_t)Bdim * NH * Sdim];         // (rowmax, 1/rowsum)
__device__ __nv_bfloat16 g_q_hi[(size_t)Bdim * NH * Sdim * HD];
__device__ __nv_bfloat16 g_q_lo[(size_t)Bdim * NH * Sdim * HD];
__device__ __nv_bfloat16 g_k_hi[(size_t)Bdim * NH * Sdim * HD];
__device__ __nv_bfloat16 g_k_lo[(size_t)Bdim * NH * Sdim * HD];
__device__ __nv_bfloat16 g_v_hi[(size_t)Bdim * Sdim * Hdim];
__device__ __nv_bfloat16 g_v_lo[(size_t)Bdim * Sdim * Hdim];

// ---- packed f32x2 helpers ---------------------------------------------------
__device__ __forceinline__ void fma2(ull& d, ull a, ull b) {
    asm("fma.rn.f32x2 %0, %1, %2, %0;" : "+l"(d) : "l"(a), "l"(b));
}
__device__ __forceinline__ ull dup2(float v) {
    ull r;
    asm("mov.b64 %0, {%1, %1};" : "=l"(r) : "f"(v));
    return r;
}
__device__ __forceinline__ float2 unpk(ull v) {
    float2 r;
    asm("mov.b64 {%0, %1}, %2;" : "=f"(r.x), "=f"(r.y) : "l"(v));
    return r;
}

// ---- mma.sync / ldmatrix helpers ---------------------------------------------
__device__ __forceinline__ uint32_t smem_u32(const void* p) {
    uint32_t a;
    asm("{ .reg .u64 t; cvta.to.shared.u64 t, %1; cvt.u32.u64 %0, t; }" : "=r"(a) : "l"(p));
    return a;
}
__device__ __forceinline__ void ldsm_x4(uint32_t* r, uint32_t addr) {
    asm volatile("ldmatrix.sync.aligned.m8n8.x4.shared.b16 {%0,%1,%2,%3}, [%4];"
                 : "=r"(r[0]), "=r"(r[1]), "=r"(r[2]), "=r"(r[3]) : "r"(addr));
}
__device__ __forceinline__ void ldsm_x2(uint32_t* r, uint32_t addr) {
    asm volatile("ldmatrix.sync.aligned.m8n8.x2.shared.b16 {%0,%1}, [%2];"
                 : "=r"(r[0]), "=r"(r[1]) : "r"(addr));
}
__device__ __forceinline__ void ldsm_x2t(uint32_t* r, uint32_t addr) {
    asm volatile("ldmatrix.sync.aligned.m8n8.x2.trans.shared.b16 {%0,%1}, [%2];"
                 : "=r"(r[0]), "=r"(r[1]) : "r"(addr));
}
__device__ __forceinline__ void mma_bf16(float* d, const uint32_t* a, const uint32_t* b) {
    asm volatile("mma.sync.aligned.m16n8k16.row.col.f32.bf16.bf16.f32 "
                 "{%0,%1,%2,%3}, {%4,%5,%6,%7}, {%8,%9}, {%0,%1,%2,%3};"
                 : "+f"(d[0]), "+f"(d[1]), "+f"(d[2]), "+f"(d[3])
                 : "r"(a[0]), "r"(a[1]), "r"(a[2]), "r"(a[3]), "r"(b[0]), "r"(b[1]));
}
__device__ __forceinline__ uint32_t pack_bf16x2(float e0, float e1) {
    uint32_t r;  // lower half = e0, upper = e1
    asm("cvt.rn.bf16x2.f32 %0, %2, %1;" : "=r"(r) : "f"(e0), "f"(e1));
    return r;
}
__device__ __forceinline__ void split8(const float* v, uint4& hi, uint4& lo) {
    uint32_t hw[4], lw[4];
#pragma unroll
    for (int j = 0; j < 4; j++) {
        float e0 = v[2 * j], e1 = v[2 * j + 1];
        uint32_t h = pack_bf16x2(e0, e1);
        float f0 = __uint_as_float(h << 16);
        float f1 = __uint_as_float(h & 0xffff0000u);
        hw[j] = h;
        lw[j] = pack_bf16x2(e0 - f0, e1 - f1);
    }
    hi = make_uint4(hw[0], hw[1], hw[2], hw[3]);
    lo = make_uint4(lw[0], lw[1], lw[2], lw[3]);
}
__device__ __forceinline__ void cp_async16(uint32_t saddr, const void* gptr) {
    asm volatile("cp.async.cg.shared.global [%0], [%1], 16;" :: "r"(saddr), "l"(gptr));
}
#define CP_COMMIT() asm volatile("cp.async.commit_group;")
#define CP_WAIT0()  asm volatile("cp.async.wait_group 0;")

#define PAD 132

// ---------------------------------------------------------------------------
// K1: QKV GEMM (FFMA2) + split-bf16 scatter epilogue.
// ---------------------------------------------------------------------------
__global__ void __launch_bounds__(256) qkv_gemm_split_kernel(
    const float* __restrict__ A, const float* __restrict__ B,
    const float* __restrict__ bias)
{
    const int N = H3, K = Hdim;
    __shared__ __align__(16) float As[2][16][PAD];
    __shared__ __align__(16) float Bs[2][16][PAD];

    const int tid = threadIdx.x;
    const int tx = tid & 15, ty = tid >> 4;
    const int m0 = blockIdx.y * 128;
    const int n0 = blockIdx.x * 128;
    const int lrow = tid >> 2;
    const int lkq  = tid & 3;
    (void)N;

    ull acc[4][8];
#pragma unroll
    for (int i = 0; i < 4; i++)
#pragma unroll
        for (int j = 0; j < 8; j++) acc[i][j] = 0ull;

    float4 ra0, ra1, rb0, rb1;
    const int nchunks = K >> 4;

#define G_LDG(kc)                                                                 \
    ra0 = *(const float4*)&A[(size_t)(m0 + lrow)      * K + (kc) + lkq * 4];      \
    ra1 = *(const float4*)&A[(size_t)(m0 + lrow + 64) * K + (kc) + lkq * 4];      \
    rb0 = *(const float4*)&B[(size_t)(n0 + lrow)      * K + (kc) + lkq * 4];      \
    rb1 = *(const float4*)&B[(size_t)(n0 + lrow + 64) * K + (kc) + lkq * 4];

#define G_STS(st)                                                                 \
    As[st][lkq * 4 + 0][lrow] = ra0.x; As[st][lkq * 4 + 1][lrow] = ra0.y;         \
    As[st][lkq * 4 + 2][lrow] = ra0.z; As[st][lkq * 4 + 3][lrow] = ra0.w;         \
    As[st][lkq * 4 + 0][lrow + 64] = ra1.x; As[st][lkq * 4 + 1][lrow + 64] = ra1.y;\
    As[st][lkq * 4 + 2][lrow + 64] = ra1.z; As[st][lkq * 4 + 3][lrow + 64] = ra1.w;\
    Bs[st][lkq * 4 + 0][lrow] = rb0.x; Bs[st][lkq * 4 + 1][lrow] = rb0.y;         \
    Bs[st][lkq * 4 + 2][lrow] = rb0.z; Bs[st][lkq * 4 + 3][lrow] = rb0.w;         \
    Bs[st][lkq * 4 + 0][lrow + 64] = rb1.x; Bs[st][lkq * 4 + 1][lrow + 64] = rb1.y;\
    Bs[st][lkq * 4 + 2][lrow + 64] = rb1.z; Bs[st][lkq * 4 + 3][lrow + 64] = rb1.w;

    G_LDG(0)
    G_STS(0)
    __syncthreads();

    for (int c = 0; c < nchunks; c++) {
        const int st = c & 1;
        if (c + 1 < nchunks) { G_LDG((c + 1) << 4) }
#pragma unroll
        for (int kk = 0; kk < 16; kk++) {
            const ull* ap = (const ull*)&As[st][kk][ty * 8];
            ull a0 = ap[0], a1 = ap[1], a2 = ap[2], a3 = ap[3];
            float4 b0 = *(const float4*)&Bs[st][kk][tx * 8];
            float4 b1 = *(const float4*)&Bs[st][kk][tx * 8 + 4];
            ull bb[8] = {dup2(b0.x), dup2(b0.y), dup2(b0.z), dup2(b0.w),
                         dup2(b1.x), dup2(b1.y), dup2(b1.z), dup2(b1.w)};
#pragma unroll
            for (int j = 0; j < 8; j++) {
                fma2(acc[0][j], a0, bb[j]);
                fma2(acc[1][j], a1, bb[j]);
                fma2(acc[2][j], a2, bb[j]);
                fma2(acc[3][j], a3, bb[j]);
            }
        }
        if (c + 1 < nchunks) { G_STS(st ^ 1) }
        __syncthreads();
    }

    const int nb = n0 + tx * 8;
    float bb8[8];
#pragma unroll
    for (int j = 0; j < 8; j++) bb8[j] = bias[nb + j];

    const int region = nb >> 9;
    const int head   = (nb >> 6) & 7;
    const int d0     = nb & 63;

#pragma unroll
    for (int i = 0; i < 4; i++) {
        int mbase = m0 + ty * 8 + 2 * i;
#pragma unroll
        for (int p = 0; p < 2; p++) {
            float v[8];
#pragma unroll
            for (int j = 0; j < 8; j++) {
                float2 cj = unpk(acc[i][j]);
                v[j] = (p ? cj.y : cj.x) + bb8[j];
            }
            uint4 hi, lo;
            split8(v, hi, lo);
            int mm = mbase + p;
            int b = mm >> 11, s = mm & 2047;
            if (region == 0) {
                size_t off = ((size_t)(b * NH + head) * Sdim + s) * HD + d0;
                *(uint4*)&g_q_hi[off] = hi;
                *(uint4*)&g_q_lo[off] = lo;
            } else if (region == 1) {
                size_t off = ((size_t)(b * NH + head) * Sdim + s) * HD + d0;
                *(uint4*)&g_k_hi[off] = hi;
                *(uint4*)&g_k_lo[off] = lo;
            } else {
                size_t off = ((size_t)b * Sdim + s) * Hdim + head * HD + d0;
                *(uint4*)&g_v_hi[off] = hi;
                *(uint4*)&g_v_lo[off] = lo;
            }
        }
    }
}

// ---------------------------------------------------------------------------
// K2: scores via mma.sync bf16 (3-term split). (unchanged from round 5)
// ---------------------------------------------------------------------------
#define SQS 72
#define SC_ARR (128 * SQS)
#define SC_SMEM (4 * SC_ARR * 2 + 128 * 3 * 4 * 2 + 128 * 4)

__global__ void __launch_bounds__(256) scores_mma_kernel(
    const float* __restrict__ pos, const int* __restrict__ mask)
{
    extern __shared__ __align__(16) char sm[];
    __nv_bfloat16* Qh = (__nv_bfloat16*)sm;
    __nv_bfloat16* Ql = Qh + SC_ARR;
    __nv_bfloat16* Kh = Qh + 2 * SC_ARR;
    __nv_bfloat16* Kl = Qh + 3 * SC_ARR;
    float* Pq = (float*)(sm + 4 * SC_ARR * 2);
    float* Pk = Pq + 128 * 3;
    int*   Mk = (int*)(Pk + 128 * 3);

    const int tid = threadIdx.x, lane = tid & 31, wid = tid >> 5;
    const int bh = blockIdx.z, b = bh >> 3;
    const int q0 = blockIdx.y * 128, k0 = blockIdx.x * 128;

    const __nv_bfloat16* sQh = g_q_hi + ((size_t)bh * Sdim + q0) * HD;
    const __nv_bfloat16* sQl = g_q_lo + ((size_t)bh * Sdim + q0) * HD;
    const __nv_bfloat16* sKh = g_k_hi + ((size_t)bh * Sdim + k0) * HD;
    const __nv_bfloat16* sKl = g_k_lo + ((size_t)bh * Sdim + k0) * HD;

#pragma unroll
    for (int i = 0; i < 4; i++) {
        int idx = tid + 256 * i;
        int r = idx >> 3, c = idx & 7;
        *(uint4*)&Qh[r * SQS + c * 8] = *(const uint4*)&sQh[(size_t)r * HD + c * 8];
        *(uint4*)&Ql[r * SQS + c * 8] = *(const uint4*)&sQl[(size_t)r * HD + c * 8];
        *(uint4*)&Kh[r * SQS + c * 8] = *(const uint4*)&sKh[(size_t)r * HD + c * 8];
        *(uint4*)&Kl[r * SQS + c * 8] = *(const uint4*)&sKl[(size_t)r * HD + c * 8];
    }
    if (tid < 128) {
        Pq[tid * 3 + 0] = pos[(size_t)(b * Sdim + q0 + tid) * 3 + 0];
        Pq[tid * 3 + 1] = pos[(size_t)(b * Sdim + q0 + tid) * 3 + 1];
        Pq[tid * 3 + 2] = pos[(size_t)(b * Sdim + q0 + tid) * 3 + 2];
    } else {
        int t2 = tid - 128;
        Pk[t2 * 3 + 0] = pos[(size_t)(b * Sdim + k0 + t2) * 3 + 0];
        Pk[t2 * 3 + 1] = pos[(size_t)(b * Sdim + k0 + t2) * 3 + 1];
        Pk[t2 * 3 + 2] = pos[(size_t)(b * Sdim + k0 + t2) * 3 + 2];
        Mk[t2]         = mask[b * Sdim + k0 + t2];
    }
    __syncthreads();

    const int wm = wid & 3, wn = wid >> 2;
    const uint32_t qb = smem_u32(Qh);
    const uint32_t kb = smem_u32(Kh);
    const uint32_t LOFF = SC_ARR * 2;

    float d[2][8][4];
#pragma unroll
    for (int mt = 0; mt < 2; mt++)
#pragma unroll
        for (int nt = 0; nt < 8; nt++)
#pragma unroll
            for (int e = 0; e < 4; e++) d[mt][nt][e] = 0.f;

#pragma unroll
    for (int ks = 0; ks < 4; ks++) {
        uint32_t ah[2][4], al[2][4];
#pragma unroll
        for (int mt = 0; mt < 2; mt++) {
            int row = wm * 32 + mt * 16 + (lane & 15);
            int col = ks * 16 + (lane >> 4) * 8;
            uint32_t adr = qb + (row * SQS + col) * 2;
            ldsm_x4(ah[mt], adr);
            ldsm_x4(al[mt], adr + LOFF);
        }
        uint32_t bhf[8][2], blf[8][2];
#pragma unroll
        for (int nt = 0; nt < 8; nt++) {
            int row = wn * 64 + nt * 8 + (lane & 7);
            int col = ks * 16 + ((lane >> 3) & 1) * 8;
            uint32_t adr = kb + (row * SQS + col) * 2;
            ldsm_x2(bhf[nt], adr);
            ldsm_x2(blf[nt], adr + LOFF);
        }
#pragma unroll
        for (int mt = 0; mt < 2; mt++)
#pragma unroll
            for (int nt = 0; nt < 8; nt++) {
                mma_bf16(d[mt][nt], ah[mt], bhf[nt]);
                mma_bf16(d[mt][nt], ah[mt], blf[nt]);
                mma_bf16(d[mt][nt], al[mt], bhf[nt]);
            }
    }

    const int g = lane >> 2, tig = lane & 3;
#pragma unroll
    for (int mt = 0; mt < 2; mt++) {
#pragma unroll
        for (int hf = 0; hf < 2; hf++) {
            int lr = wm * 32 + mt * 16 + g + hf * 8;
            float px = Pq[lr * 3 + 0], py = Pq[lr * 3 + 1], pz = Pq[lr * 3 + 2];
            float* orow = &g_scores[((size_t)bh * Sdim + q0 + lr) * Sdim + k0];
#pragma unroll
            for (int nt = 0; nt < 8; nt++) {
                int lc = wn * 64 + nt * 8 + tig * 2;
                float v0 = d[mt][nt][hf * 2 + 0];
                float v1 = d[mt][nt][hf * 2 + 1];
                float dx0 = px - Pk[lc * 3 + 0], dy0 = py - Pk[lc * 3 + 1], dz0 = pz - Pk[lc * 3 + 2];
                float dx1 = px - Pk[lc * 3 + 3], dy1 = py - Pk[lc * 3 + 4], dz1 = pz - Pk[lc * 3 + 5];
                float s0 = 0.125f * (v0 - (dx0 * dx0 + dy0 * dy0 + dz0 * dz0));
                float s1 = 0.125f * (v1 - (dx1 * dx1 + dy1 * dy1 + dz1 * dz1));
                if (Mk[lc] == 0)     s0 = -1e30f;
                if (Mk[lc + 1] == 0) s1 = -1e30f;
                float2 o = {s0, s1};
                *(float2*)&orow[lc] = o;
            }
        }
    }
}

// ---------------------------------------------------------------------------
// K3: row stats (max, 1/sum) + head-mean. No weight write-back.
// ---------------------------------------------------------------------------
__global__ void __launch_bounds__(256) stats_mean_kernel(float* __restrict__ mean_out)
{
    const int bq = blockIdx.x;
    const int b = bq >> 11, q = bq & 2047;
    const int tid = threadIdx.x;
    const int lane = tid & 31, wid = tid >> 5;
    const int kbase = tid * 8;

    __shared__ float red[8];

    float macc[8];
#pragma unroll
    for (int j = 0; j < 8; j++) macc[j] = 0.f;

    for (int h = 0; h < NH; h++) {
        const float* row = g_scores + ((size_t)((b * NH + h) * Sdim + q)) * Sdim;
        float4 v0 = *(const float4*)&row[kbase];
        float4 v1 = *(const float4*)&row[kbase + 4];
        float v[8] = {v0.x, v0.y, v0.z, v0.w, v1.x, v1.y, v1.z, v1.w};

        float m = v[0];
#pragma unroll
        for (int j = 1; j < 8; j++) m = fmaxf(m, v[j]);
#pragma unroll
        for (int off = 16; off > 0; off >>= 1)
            m = fmaxf(m, __shfl_xor_sync(0xffffffffu, m, off));
        if (lane == 0) red[wid] = m;
        __syncthreads();
        m = red[0];
#pragma unroll
        for (int w = 1; w < 8; w++) m = fmaxf(m, red[w]);
        __syncthreads();

        float e[8];
        float s = 0.f;
#pragma unroll
        for (int j = 0; j < 8; j++) { e[j] = __expf(v[j] - m); s += e[j]; }
#pragma unroll
        for (int off = 16; off > 0; off >>= 1)
            s += __shfl_xor_sync(0xffffffffu, s, off);
        if (lane == 0) red[wid] = s;
        __syncthreads();
        s = red[0];
#pragma unroll
        for (int w = 1; w < 8; w++) s += red[w];

        float inv = 1.0f / s;
        if (tid == 0)
            g_stats[(size_t)(b * NH + h) * Sdim + q] = make_float2(m, inv);
#pragma unroll
        for (int j = 0; j < 8; j++) macc[j] += e[j] * inv;
        __syncthreads();
    }

    float* mrow = mean_out + ((size_t)(b * Sdim + q)) * Sdim + kbase;
    float4 m0 = {macc[0] * 0.125f, macc[1] * 0.125f, macc[2] * 0.125f, macc[3] * 0.125f};
    float4 m1 = {macc[4] * 0.125f, macc[5] * 0.125f, macc[6] * 0.125f, macc[7] * 0.125f};
    *(float4*)&mrow[0] = m0;
    *(float4*)&mrow[4] = m1;
}

// ---------------------------------------------------------------------------
// K4: pv via mma.sync bf16 (3-term). Weights computed on the fly:
// w = expf(score - m) * inv, split to bf16 hi/lo during STS.
// 128B smem rows + XOR-16 swizzle; V via cp.async; 2 CTAs/SM.
// smem layout (bytes): [0,1024) stats; stage st at 1024 + st*49152:
//   Wh +0 (16384) | Wl +16384 (16384) | Vh +32768 (8192) | Vl +40960 (8192)
// ---------------------------------------------------------------------------
#define PV_STAGE_B 49152
#define PV_WL_OFF  16384
#define PV_VH_OFF  32768
#define PV_VL_OFF  40960
#define PV_BASE    1024
#define PV_SMEM_B  (PV_BASE + 2 * PV_STAGE_B)   // 99328

__global__ void __launch_bounds__(256, 2) pv_mma_kernel()
{
    extern __shared__ __align__(16) char sm[];
    float2* stats_s = (float2*)sm;

    const int tid = threadIdx.x, lane = tid & 31, wid = tid >> 5;
    const int bh = blockIdx.y, b = bh >> 3, h = bh & 7;
    const int q0 = blockIdx.x * 128;

    const float* Sp = g_scores + (size_t)bh * Sdim * Sdim + (size_t)q0 * Sdim;
    const __nv_bfloat16* Vh_src = g_v_hi + (size_t)b * Sdim * Hdim + h * HD;
    const __nv_bfloat16* Vl_src = g_v_lo + (size_t)b * Sdim * Hdim + h * HD;

    const uint32_t sb = smem_u32(sm);
    const int wm = wid & 3, wn = wid >> 2;

    if (tid < 128)
        stats_s[tid] = g_stats[(size_t)bh * Sdim + q0 + tid];

    float d[2][4][4];
#pragma unroll
    for (int mt = 0; mt < 2; mt++)
#pragma unroll
        for (int nt = 0; nt < 4; nt++)
#pragma unroll
            for (int e = 0; e < 4; e++) d[mt][nt][e] = 0.f;

    float4 rs[8];

    // V chunk (64k x 64d bf16 hi+lo) via cp.async into stage st
#define PV_CPV(kc, st)                                                            \
    _Pragma("unroll") for (int i = 0; i < 2; i++) {                               \
        int idx = tid + 256 * i; int kk = idx >> 3, c8 = idx & 7;                 \
        uint32_t soff = kk * 128 + ((c8 * 16) ^ ((kk & 7) * 16));                 \
        cp_async16(sb + PV_BASE + (st) * PV_STAGE_B + PV_VH_OFF + soff,           \
                   &Vh_src[(size_t)((kc) + kk) * Hdim + c8 * 8]);                 \
        cp_async16(sb + PV_BASE + (st) * PV_STAGE_B + PV_VL_OFF + soff,           \
                   &Vl_src[(size_t)((kc) + kk) * Hdim + c8 * 8]);                 \
    }                                                                             \
    CP_COMMIT();

#define PV_LDGW(kc)                                                               \
    _Pragma("unroll") for (int i = 0; i < 8; i++) {                               \
        int idx = tid + 256 * i; int r = idx >> 4, cc = idx & 15;                 \
        rs[i] = *(const float4*)&Sp[(size_t)r * Sdim + (kc) + cc * 4];            \
    }

#define PV_STSW(st)                                                               \
    _Pragma("unroll") for (int i = 0; i < 8; i++) {                               \
        int idx = tid + 256 * i; int r = idx >> 4, cc = idx & 15;                 \
        float2 stt = stats_s[r];                                                  \
        float w0 = __expf(rs[i].x - stt.x) * stt.y;                               \
        float w1 = __expf(rs[i].y - stt.x) * stt.y;                               \
        float w2 = __expf(rs[i].z - stt.x) * stt.y;                               \
        float w3 = __expf(rs[i].w - stt.x) * stt.y;                               \
        uint32_t h01 = pack_bf16x2(w0, w1);                                       \
        uint32_t h23 = pack_bf16x2(w2, w3);                                       \
        float r0 = w0 - __uint_as_float(h01 << 16);                               \
        float r1 = w1 - __uint_as_float(h01 & 0xffff0000u);                       \
        float r2 = w2 - __uint_as_float(h23 << 16);                               \
        float r3 = w3 - __uint_as_float(h23 & 0xffff0000u);                       \
        uint32_t l01 = pack_bf16x2(r0, r1);                                       \
        uint32_t l23 = pack_bf16x2(r2, r3);                                       \
        uint32_t soff = r * 128 + ((cc * 8) ^ ((r & 7) * 16));                    \
        char* wb_ = sm + PV_BASE + (st) * PV_STAGE_B;                             \
        *(uint2*)(wb_ + soff)             = make_uint2(h01, h23);                 \
        *(uint2*)(wb_ + PV_WL_OFF + soff) = make_uint2(l01, l23);                 \
    }

    // prologue: stage 0
    PV_CPV(0, 0)
    PV_LDGW(0)
    __syncthreads();          // stats_s visible
    PV_STSW(0)
    CP_WAIT0();
    __syncthreads();

    for (int c = 0; c < 32; c++) {
        const int st = c & 1;
        if (c < 31) {
            PV_CPV((c + 1) * 64, st ^ 1)
            PV_LDGW((c + 1) * 64)
        }
        // compute on stage st
        {
            const uint32_t wbase = sb + PV_BASE + st * PV_STAGE_B;
            const uint32_t vbase = wbase + PV_VH_OFF;
#pragma unroll
            for (int ks = 0; ks < 4; ks++) {
                uint32_t ah[2][4], al[2][4];
#pragma unroll
                for (int mt = 0; mt < 2; mt++) {
                    int row = wm * 32 + mt * 16 + (lane & 15);
                    uint32_t colb = (ks * 16 + (lane >> 4) * 8) * 2;
                    uint32_t adr = wbase + row * 128 + (colb ^ ((row & 7) * 16));
                    ldsm_x4(ah[mt], adr);
                    ldsm_x4(al[mt], adr + PV_WL_OFF);
                }
                uint32_t bhf[4][2], blf[4][2];
#pragma unroll
                for (int nt = 0; nt < 4; nt++) {
                    int rowk = ks * 16 + (lane & 15);
                    uint32_t colb = (wn * 32 + nt * 8) * 2;
                    uint32_t adr = vbase + rowk * 128 + (colb ^ ((rowk & 7) * 16));
                    ldsm_x2t(bhf[nt], adr);
                    ldsm_x2t(blf[nt], adr + (PV_VL_OFF - PV_VH_OFF));
                }
#pragma unroll
                for (int mt = 0; mt < 2; mt++)
#pragma unroll
                    for (int nt = 0; nt < 4; nt++) {
                        mma_bf16(d[mt][nt], ah[mt], bhf[nt]);
                        mma_bf16(d[mt][nt], ah[mt], blf[nt]);
                        mma_bf16(d[mt][nt], al[mt], bhf[nt]);
                    }
            }
        }
        __syncthreads();
        if (c < 31) {
            PV_STSW(st ^ 1)
            CP_WAIT0();
        }
        __syncthreads();
    }

    const int g = lane >> 2, tig = lane & 3;
#pragma unroll
    for (int mt = 0; mt < 2; mt++)
#pragma unroll
        for (int nt = 0; nt < 4; nt++)
#pragma unroll
            for (int hf = 0; hf < 2; hf++) {
                int r = q0 + wm * 32 + mt * 16 + g + hf * 8;
                int col = h * HD + wn * 32 + nt * 8 + tig * 2;
                float2 o = {d[mt][nt][hf * 2 + 0], d[mt][nt][hf * 2 + 1]};
                *(float2*)&g_ctx[(size_t)(b * Sdim + r) * Hdim + col] = o;
            }
}

// ---------------------------------------------------------------------------
// K5: generic C = A @ B^T + bias (FFMA2)
// ---------------------------------------------------------------------------
__global__ void __launch_bounds__(256) gemm_abT_kernel(
    const float* __restrict__ A, const float* __restrict__ B,
    const float* __restrict__ bias, float* __restrict__ C,
    int M, int N, int K)
{
    __shared__ __align__(16) float As[2][16][PAD];
    __shared__ __align__(16) float Bs[2][16][PAD];

    const int tid = threadIdx.x;
    const int tx = tid & 15, ty = tid >> 4;
    const int m0 = blockIdx.y * 128;
    const int n0 = blockIdx.x * 128;
    const int lrow = tid >> 2;
    const int lkq  = tid & 3;

    ull acc[4][8];
#pragma unroll
    for (int i = 0; i < 4; i++)
#pragma unroll
        for (int j = 0; j < 8; j++) acc[i][j] = 0ull;

    float4 ra0, ra1, rb0, rb1;
    const int nchunks = K >> 4;

    G_LDG(0)
    G_STS(0)
    __syncthreads();

    for (int c = 0; c < nchunks; c++) {
        const int st = c & 1;
        if (c + 1 < nchunks) { G_LDG((c + 1) << 4) }
#pragma unroll
        for (int kk = 0; kk < 16; kk++) {
            const ull* ap = (const ull*)&As[st][kk][ty * 8];
            ull a0 = ap[0], a1 = ap[1], a2 = ap[2], a3 = ap[3];
            float4 b0 = *(const float4*)&Bs[st][kk][tx * 8];
            float4 b1 = *(const float4*)&Bs[st][kk][tx * 8 + 4];
            ull bb[8] = {dup2(b0.x), dup2(b0.y), dup2(b0.z), dup2(b0.w),
                         dup2(b1.x), dup2(b1.y), dup2(b1.z), dup2(b1.w)};
#pragma unroll
            for (int j = 0; j < 8; j++) {
                fma2(acc[0][j], a0, bb[j]);
                fma2(acc[1][j], a1, bb[j]);
                fma2(acc[2][j], a2, bb[j]);
                fma2(acc[3][j], a3, bb[j]);
            }
        }
        if (c + 1 < nchunks) { G_STS(st ^ 1) }
        __syncthreads();
    }

    const int nb = n0 + tx * 8;
    float4 bv0 = *(const float4*)&bias[nb];
    float4 bv1 = *(const float4*)&bias[nb + 4];
#pragma unroll
    for (int i = 0; i < 4; i++) {
        float2 c0 = unpk(acc[i][0]), c1 = unpk(acc[i][1]);
        float2 c2 = unpk(acc[i][2]), c3 = unpk(acc[i][3]);
        float2 c4 = unpk(acc[i][4]), c5 = unpk(acc[i][5]);
        float2 c6 = unpk(acc[i][6]), c7 = unpk(acc[i][7]);
        int m = m0 + ty * 8 + 2 * i;
        float4 lo0 = {c0.x + bv0.x, c1.x + bv0.y, c2.x + bv0.z, c3.x + bv0.w};
        float4 lo1 = {c4.x + bv1.x, c5.x + bv1.y, c6.x + bv1.z, c7.x + bv1.w};
        float4 hi0 = {c0.y + bv0.x, c1.y + bv0.y, c2.y + bv0.z, c3.y + bv0.w};
        float4 hi1 = {c4.y + bv1.x, c5.y + bv1.y, c6.y + bv1.z, c7.y + bv1.w};
        *(float4*)&C[(size_t)m * N + nb]           = lo0;
        *(float4*)&C[(size_t)m * N + nb + 4]       = lo1;
        *(float4*)&C[(size_t)(m + 1) * N + nb]     = hi0;
        *(float4*)&C[(size_t)(m + 1) * N + nb + 4] = hi1;
    }
}

// ---------------------------------------------------------------------------
extern "C" void kernel_launch(void* const* d_in, const int* in_sizes, int n_in,
                              void* d_out, int out_size)
{
    const float* x     = (const float*)d_in[0];
    const float* pos   = (const float*)d_in[1];
    const int*   mask  = (const int*)d_in[2];
    const float* w_qkv = (const float*)d_in[3];
    const float* b_qkv = (const float*)d_in[4];
    const float* w_out = (const float*)d_in[5];
    const float* b_out = (const float*)d_in[6];

    float* out_proj = (float*)d_out;
    float* mean_out = out_proj + (size_t)Bdim * Sdim * Hdim;

    float* p_ctx;
    cudaGetSymbolAddress((void**)&p_ctx, g_ctx);

    cudaFuncSetAttribute(scores_mma_kernel, cudaFuncAttributeMaxDynamicSharedMemorySize, SC_SMEM);
    cudaFuncSetAttribute(pv_mma_kernel, cudaFuncAttributeMaxDynamicSharedMemorySize, PV_SMEM_B);

    // K1: QKV projection + split
    {
        dim3 grid(H3 / 128, (Bdim * Sdim) / 128);
        qkv_gemm_split_kernel<<<grid, 256>>>(x, w_qkv, b_qkv);
    }
    // K2: scores (tensor)
    {
        dim3 grid(Sdim / 128, Sdim / 128, Bdim * NH);
        scores_mma_kernel<<<grid, 256, SC_SMEM>>>(pos, mask);
    }
    // K3: stats + head-mean
    stats_mean_kernel<<<Bdim * Sdim, 256>>>(mean_out);

    // K4: ctx = softmax(W) @ V (tensor, exp on the fly)
    {
        dim3 grid(Sdim / 128, Bdim * NH);
        pv_mma_kernel<<<grid, 256, PV_SMEM_B>>>();
    }
    // K5: output projection
    {
        dim3 grid(Hdim / 128, (Bdim * Sdim) / 128);
        gemm_abT_kernel<<<grid, 256>>>(p_ctx, w_out, b_out, out_proj,
                                       Bdim * Sdim, Hdim, Hdim);
    }
}